// round 8
// baseline (speedup 1.0000x reference)
#include <cuda_runtime.h>
#include <cuda_bf16.h>
#include <math.h>
#include <stdint.h>

#define CC   256
#define NSP  16384
#define BB   8
#define EPS  1e-5f
#define KSPLIT 16

// ---------------- scratch (device globals) ----------------
__device__ __nv_bfloat16 g_xh[(size_t)BB * CC * NSP], g_xl[(size_t)BB * CC * NSP];
__device__ __nv_bfloat16 g_Eh[(size_t)BB * CC * NSP], g_El[(size_t)BB * CC * NSP];
__device__ float g_rowsum[BB * CC];
__device__ float g_Stp[(size_t)KSPLIT * BB * CC * CC];
__device__ float g_St[BB * CC * CC];
__device__ float g_R[BB * CC * CC];
__device__ float g_W2[CC * CC];
__device__ __nv_bfloat16 g_Wkh[CC * CC], g_Wkl[CC * CC];
__device__ __nv_bfloat16 g_Mh[BB * CC * CC], g_Ml[BB * CC * CC];

// ---------------- smem stage layouts (1 CTA/SM, 3-stage rings) --------------
// NN (k_exp/k_out): A [128][40] hi/lo + B(x^T) [32][264] hi/lo
#define NN_AH 0
#define NN_AL 10240
#define NN_BH 20480
#define NN_BL 37376
#define NN_STG 54272
#define NN_SMEM (3 * NN_STG)     // 162816
// NT (k_st): A [128][40] hi/lo + B [256][40] hi/lo
#define NT_AH 0
#define NT_AL 10240
#define NT_BH 20480
#define NT_BL 40960
#define NT_STG 61440
#define NT_SMEM (3 * NT_STG)     // 184320

// ---------------- helpers ----------------
__device__ __forceinline__ uint32_t smem_u32(const void* p) {
    uint32_t a;
    asm("{ .reg .u64 t; cvta.to.shared.u64 t, %1; cvt.u32.u64 %0, t; }" : "=r"(a) : "l"(p));
    return a;
}
__device__ __forceinline__ void cpa16(uint32_t dst, const void* src) {
    asm volatile("cp.async.cg.shared.global [%0], [%1], 16;" :: "r"(dst), "l"(src));
}
#define CP_COMMIT()  asm volatile("cp.async.commit_group;")
#define CP_WAIT(n)   asm volatile("cp.async.wait_group %0;" :: "n"(n))

__device__ __forceinline__ void ldm4(uint32_t* r, const void* p) {
    uint32_t a = (uint32_t)__cvta_generic_to_shared(p);
    asm volatile("ldmatrix.sync.aligned.m8n8.x4.shared.b16 {%0,%1,%2,%3},[%4];"
                 : "=r"(r[0]), "=r"(r[1]), "=r"(r[2]), "=r"(r[3]) : "r"(a));
}
__device__ __forceinline__ void ldm2(uint32_t* r, const void* p) {
    uint32_t a = (uint32_t)__cvta_generic_to_shared(p);
    asm volatile("ldmatrix.sync.aligned.m8n8.x2.shared.b16 {%0,%1},[%2];"
                 : "=r"(r[0]), "=r"(r[1]) : "r"(a));
}
__device__ __forceinline__ void ldm2t(uint32_t* r, const void* p) {
    uint32_t a = (uint32_t)__cvta_generic_to_shared(p);
    asm volatile("ldmatrix.sync.aligned.m8n8.x2.trans.shared.b16 {%0,%1},[%2];"
                 : "=r"(r[0]), "=r"(r[1]) : "r"(a));
}
__device__ __forceinline__ void mma_bf(float* d, const uint32_t* a, const uint32_t* b) {
    asm volatile("mma.sync.aligned.m16n8k16.row.col.f32.bf16.bf16.f32 "
                 "{%0,%1,%2,%3},{%4,%5,%6,%7},{%8,%9},{%0,%1,%2,%3};"
                 : "+f"(d[0]), "+f"(d[1]), "+f"(d[2]), "+f"(d[3])
                 : "r"(a[0]), "r"(a[1]), "r"(a[2]), "r"(a[3]), "r"(b[0]), "r"(b[1]));
}
__device__ __forceinline__ uint32_t pack2(float a, float b, uint32_t& lo) {
    __nv_bfloat16 ha = __float2bfloat16(a), hb = __float2bfloat16(b);
    __nv_bfloat16 la = __float2bfloat16(a - __bfloat162float(ha));
    __nv_bfloat16 lb = __float2bfloat16(b - __bfloat162float(hb));
    lo = (uint32_t)__bfloat16_as_ushort(la) | ((uint32_t)__bfloat16_as_ushort(lb) << 16);
    return (uint32_t)__bfloat16_as_ushort(ha) | ((uint32_t)__bfloat16_as_ushort(hb) << 16);
}

// ---------------- staging (cp.async pure copies) ----------------
// A: 128 rows x 32 k, smem [128][40]
__device__ __forceinline__ void stageR(uint32_t dh, uint32_t dl,
    const __nv_bfloat16* __restrict__ gh, const __nv_bfloat16* __restrict__ gl,
    size_t stride)
{
    const int r = threadIdx.x >> 1, p = threadIdx.x & 1;
    const char* s0 = (const char*)(gh + (size_t)r * stride) + p * 32;
    const char* s1 = (const char*)(gl + (size_t)r * stride) + p * 32;
    const uint32_t o = r * 80 + p * 32;
    cpa16(dh + o, s0); cpa16(dh + o + 16, s0 + 16);
    cpa16(dl + o, s1); cpa16(dl + o + 16, s1 + 16);
}
// B(NN): 32 k-rows x 256 n, smem [32][264]
__device__ __forceinline__ void stageB256(uint32_t dh, uint32_t dl,
    const __nv_bfloat16* __restrict__ gh, const __nv_bfloat16* __restrict__ gl)
{
    const int t = threadIdx.x;
    #pragma unroll
    for (int it = 0; it < 2; it++) {
        const int k = (t >> 4) + it * 16, seg = t & 15;
        const char* s0 = (const char*)(gh + (size_t)k * NSP) + seg * 32;
        const char* s1 = (const char*)(gl + (size_t)k * NSP) + seg * 32;
        const uint32_t o = k * 528 + seg * 32;
        cpa16(dh + o, s0); cpa16(dh + o + 16, s0 + 16);
        cpa16(dl + o, s1); cpa16(dl + o + 16, s1 + 16);
    }
}
// B(NT): 256 rows x 32 k, smem [256][40]
__device__ __forceinline__ void stageR256(uint32_t dh, uint32_t dl,
    const __nv_bfloat16* __restrict__ gh, const __nv_bfloat16* __restrict__ gl)
{
    const int r = threadIdx.x;
    const char* s0 = (const char*)(gh + (size_t)r * NSP);
    const char* s1 = (const char*)(gl + (size_t)r * NSP);
    const uint32_t o = r * 80;
    cpa16(dh + o, s0);      cpa16(dh + o + 16, s0 + 16);
    cpa16(dh + o + 32, s0 + 32); cpa16(dh + o + 48, s0 + 48);
    cpa16(dl + o, s1);      cpa16(dl + o + 16, s1 + 16);
    cpa16(dl + o + 32, s1 + 32); cpa16(dl + o + 48, s1 + 48);
}

// ---------------- 64x64 warp-tile compute for one 32-K chunk ----------------
template<bool BT>
__device__ __forceinline__ void computeW(const char* smb, float acc[4][8][4])
{
    const int t = threadIdx.x, lane = t & 31, w = t >> 5;
    const int wm = w & 1, wn = w >> 1;            // wm 0..1 (64 rows), wn 0..3 (64 cols)
    const int ar = wm * 64 + (lane & 15);
    const int ac = (lane >> 4) * 8;
    const int btr = lane & 15;
    const int btc = wn * 64;
    const int nrb = wn * 64 + (lane & 7);
    const int nc  = ((lane >> 3) & 1) * 8;

    const __nv_bfloat16* Ah = (const __nv_bfloat16*)(smb + NN_AH);
    const __nv_bfloat16* Al = (const __nv_bfloat16*)(smb + NN_AL);
    const __nv_bfloat16* Bh = (const __nv_bfloat16*)(smb + NN_BH);
    const __nv_bfloat16* Bl = (const __nv_bfloat16*)(smb + (BT ? NN_BL : NT_BL));

    #pragma unroll
    for (int kk = 0; kk < 2; kk++) {
        uint32_t ah[4][4], al[4][4];
        #pragma unroll
        for (int mi = 0; mi < 4; mi++) {
            ldm4(ah[mi], Ah + (ar + mi * 16) * 40 + kk * 16 + ac);
            ldm4(al[mi], Al + (ar + mi * 16) * 40 + kk * 16 + ac);
        }
        #pragma unroll
        for (int nh = 0; nh < 2; nh++) {
            uint32_t bq[4][2];
            #pragma unroll
            for (int ni = 0; ni < 4; ni++) {
                if (BT) ldm2t(bq[ni], Bh + (kk * 16 + btr) * 264 + btc + nh * 32 + ni * 8);
                else    ldm2 (bq[ni], Bh + (nrb + nh * 32 + ni * 8) * 40 + kk * 16 + nc);
            }
            #pragma unroll
            for (int mi = 0; mi < 4; mi++)
                #pragma unroll
                for (int ni = 0; ni < 4; ni++)
                    mma_bf(acc[mi][nh * 4 + ni], ah[mi], bq[ni]);
            #pragma unroll
            for (int mi = 0; mi < 4; mi++)
                #pragma unroll
                for (int ni = 0; ni < 4; ni++)
                    mma_bf(acc[mi][nh * 4 + ni], al[mi], bq[ni]);
            #pragma unroll
            for (int ni = 0; ni < 4; ni++) {
                if (BT) ldm2t(bq[ni], Bl + (kk * 16 + btr) * 264 + btc + nh * 32 + ni * 8);
                else    ldm2 (bq[ni], Bl + (nrb + nh * 32 + ni * 8) * 40 + kk * 16 + nc);
            }
            #pragma unroll
            for (int mi = 0; mi < 4; mi++)
                #pragma unroll
                for (int ni = 0; ni < 4; ni++)
                    mma_bf(acc[mi][nh * 4 + ni], ah[mi], bq[ni]);
        }
    }
}

#define ACC_ZERO8(acc) { \
    _Pragma("unroll") for (int _a = 0; _a < 4; _a++) \
    _Pragma("unroll") for (int _c = 0; _c < 8; _c++) \
    _Pragma("unroll") for (int _d = 0; _d < 4; _d++) acc[_a][_c][_d] = 0.f; }

// 3-stage, 1-sync mainloop for NN kernels (8 chunks of K=32)
#define NN_MAINLOOP(Agh, Agl, Bgh, Bgl) { \
    stageR(sb + NN_AH, sb + NN_AL, Agh, Agl, CC); \
    stageB256(sb + NN_BH, sb + NN_BL, Bgh, Bgl); \
    CP_COMMIT(); \
    stageR(sb + NN_STG + NN_AH, sb + NN_STG + NN_AL, Agh + 32, Agl + 32, CC); \
    stageB256(sb + NN_STG + NN_BH, sb + NN_STG + NN_BL, \
              Bgh + (size_t)32 * NSP, Bgl + (size_t)32 * NSP); \
    CP_COMMIT(); \
    _Pragma("unroll 1") \
    for (int ch = 0; ch < 8; ch++) { \
        if (ch < 7) { CP_WAIT(1); } else { CP_WAIT(0); } \
        __syncthreads(); \
        if (ch + 2 < 8) { \
            const int kn = (ch + 2) * 32; \
            const uint32_t bb = sb + ((ch + 2) % 3) * NN_STG; \
            stageR(bb + NN_AH, bb + NN_AL, Agh + kn, Agl + kn, CC); \
            stageB256(bb + NN_BH, bb + NN_BL, \
                      Bgh + (size_t)kn * NSP, Bgl + (size_t)kn * NSP); \
            CP_COMMIT(); \
        } \
        computeW<true>(sm + (ch % 3) * NN_STG, acc); \
    } }

// ---------------- K1: E = exp(Wk @ x) + rowsums ----------------
__global__ void __launch_bounds__(256, 1)
k_exp()
{
    extern __shared__ char sm[];
    const uint32_t sb = smem_u32(sm);
    const int b = blockIdx.z, m0 = blockIdx.y * 128, n0 = blockIdx.x * 256;

    const __nv_bfloat16* Agh = g_Wkh + (size_t)m0 * CC;
    const __nv_bfloat16* Agl = g_Wkl + (size_t)m0 * CC;
    const __nv_bfloat16* Bgh = g_xh + (size_t)b * CC * NSP + n0;
    const __nv_bfloat16* Bgl = g_xl + (size_t)b * CC * NSP + n0;

    float acc[4][8][4]; ACC_ZERO8(acc);
    NN_MAINLOOP(Agh, Agl, Bgh, Bgl);

    const int t = threadIdx.x, lane = t & 31, w = t >> 5;
    const int wm = w & 1, wn = w >> 1;
    const int rbase = m0 + wm * 64 + (lane >> 2);
    const int cbase = n0 + wn * 64 + (lane & 3) * 2;
    __nv_bfloat16* Eh = g_Eh + (size_t)b * CC * NSP;
    __nv_bfloat16* El = g_El + (size_t)b * CC * NSP;

    float rs[8] = {0, 0, 0, 0, 0, 0, 0, 0};
    #pragma unroll
    for (int mi = 0; mi < 4; mi++)
        #pragma unroll
        for (int h = 0; h < 2; h++) {
            const int rr = rbase + mi * 16 + 8 * h;
            #pragma unroll
            for (int ni = 0; ni < 8; ni++) {
                float e0 = __expf(acc[mi][ni][2 * h + 0]);
                float e1 = __expf(acc[mi][ni][2 * h + 1]);
                rs[mi * 2 + h] += e0 + e1;
                uint32_t lp, hp = pack2(e0, e1, lp);
                const size_t off = (size_t)rr * NSP + cbase + ni * 8;
                *(uint32_t*)(Eh + off) = hp;
                *(uint32_t*)(El + off) = lp;
            }
        }
    #pragma unroll
    for (int i = 0; i < 8; i++) {
        float v = rs[i];
        v += __shfl_xor_sync(0xffffffffu, v, 1);
        v += __shfl_xor_sync(0xffffffffu, v, 2);
        if ((lane & 3) == 0) {
            const int rr = rbase + (i >> 1) * 16 + 8 * (i & 1);
            atomicAdd(&g_rowsum[b * CC + rr], v);
        }
    }
}

// ---------------- K5: out = relu(M @ x + bias) ----------------
__global__ void __launch_bounds__(256, 1)
k_out(const float* __restrict__ gamma, const float* __restrict__ beta,
      const float* __restrict__ mean,  const float* __restrict__ var,
      float* __restrict__ out)
{
    extern __shared__ char sm[];
    const uint32_t sb = smem_u32(sm);
    const int b = blockIdx.z, m0 = blockIdx.y * 128, n0 = blockIdx.x * 256;

    const __nv_bfloat16* Agh = g_Mh + (size_t)b * CC * CC + (size_t)m0 * CC;
    const __nv_bfloat16* Agl = g_Ml + (size_t)b * CC * CC + (size_t)m0 * CC;
    const __nv_bfloat16* Bgh = g_xh + (size_t)b * CC * NSP + n0;
    const __nv_bfloat16* Bgl = g_xl + (size_t)b * CC * NSP + n0;

    float acc[4][8][4]; ACC_ZERO8(acc);
    NN_MAINLOOP(Agh, Agl, Bgh, Bgl);

    const int t = threadIdx.x, lane = t & 31, w = t >> 5;
    const int wm = w & 1, wn = w >> 1;
    const int rbase = m0 + wm * 64 + (lane >> 2);
    const int cbase = n0 + wn * 64 + (lane & 3) * 2;
    float* Ob = out + (size_t)b * CC * NSP;

    #pragma unroll
    for (int mi = 0; mi < 4; mi++)
        #pragma unroll
        for (int h = 0; h < 2; h++) {
            const int o = rbase + mi * 16 + 8 * h;
            const float inv  = gamma[o] * rsqrtf(var[o] + EPS);
            const float bias = beta[o] - mean[o] * inv;
            #pragma unroll
            for (int ni = 0; ni < 8; ni++) {
                float2 v;
                v.x = fmaxf(acc[mi][ni][2 * h + 0] + bias, 0.f);
                v.y = fmaxf(acc[mi][ni][2 * h + 1] + bias, 0.f);
                *(float2*)(Ob + (size_t)o * NSP + cbase + ni * 8) = v;
            }
        }
}

// ---------------- K2: St partial slabs (atomic-free, 3-stage) ---------------
__global__ void __launch_bounds__(256, 1)
k_st()
{
    extern __shared__ char sm[];
    const uint32_t sb = smem_u32(sm);
    const int e0 = blockIdx.y * 128;
    const int b = blockIdx.z >> 4, ks = blockIdx.z & 15;
    const int kbeg = ks * (NSP / KSPLIT);   // 1024
    const int NCH = (NSP / KSPLIT) / 32;    // 32

    const __nv_bfloat16* Agh = g_xh + (size_t)(b * CC + e0) * NSP + kbeg;
    const __nv_bfloat16* Agl = g_xl + (size_t)(b * CC + e0) * NSP + kbeg;
    const __nv_bfloat16* Bgh = g_Eh + (size_t)b * CC * NSP + kbeg;
    const __nv_bfloat16* Bgl = g_El + (size_t)b * CC * NSP + kbeg;

    float acc[4][8][4]; ACC_ZERO8(acc);

    stageR(sb + NT_AH, sb + NT_AL, Agh, Agl, NSP);
    stageR256(sb + NT_BH, sb + NT_BL, Bgh, Bgl);
    CP_COMMIT();
    stageR(sb + NT_STG + NT_AH, sb + NT_STG + NT_AL, Agh + 32, Agl + 32, NSP);
    stageR256(sb + NT_STG + NT_BH, sb + NT_STG + NT_BL, Bgh + 32, Bgl + 32);
    CP_COMMIT();
    #pragma unroll 1
    for (int ch = 0; ch < NCH; ch++) {
        if (ch + 1 < NCH) { CP_WAIT(1); } else { CP_WAIT(0); }
        __syncthreads();
        if (ch + 2 < NCH) {
            const int kn = (ch + 2) * 32;
            const uint32_t bb = sb + ((ch + 2) % 3) * NT_STG;
            stageR(bb + NT_AH, bb + NT_AL, Agh + kn, Agl + kn, NSP);
            stageR256(bb + NT_BH, bb + NT_BL, Bgh + kn, Bgl + kn);
            CP_COMMIT();
        }
        computeW<false>(sm + (ch % 3) * NT_STG, acc);
    }

    const int t = threadIdx.x, lane = t & 31, w = t >> 5;
    const int wm = w & 1, wn = w >> 1;
    const int rbase = e0 + wm * 64 + (lane >> 2);
    const int cbase = wn * 64 + (lane & 3) * 2;
    float* Sp = g_Stp + ((size_t)ks * BB + b) * CC * CC;

    #pragma unroll
    for (int mi = 0; mi < 4; mi++)
        #pragma unroll
        for (int h = 0; h < 2; h++) {
            const int rr = rbase + mi * 16 + 8 * h;
            #pragma unroll
            for (int ni = 0; ni < 8; ni++) {
                float2 v;
                v.x = acc[mi][ni][2 * h + 0];
                v.y = acc[mi][ni][2 * h + 1];
                *(float2*)(Sp + (size_t)rr * CC + cbase + ni * 8) = v;
            }
        }
}

// ---------------- reduce slabs (float4) ----------------
__global__ void k_sum()
{
    const size_t i = ((size_t)blockIdx.x * 256 + threadIdx.x) * 4;
    const size_t STRIDE = (size_t)BB * CC * CC;
    float4 s = make_float4(0.f, 0.f, 0.f, 0.f);
    #pragma unroll
    for (int ks = 0; ks < KSPLIT; ks++) {
        float4 v = *(const float4*)(g_Stp + ks * STRIDE + i);
        s.x += v.x; s.y += v.y; s.z += v.z; s.w += v.w;
    }
    *(float4*)(g_St + i) = s;
}

// ---------------- prep: split x and Wk to bf16 hi/lo ----------------
__global__ void k_prep_x(const float* __restrict__ x)
{
    const size_t i = (size_t)blockIdx.x * 256 + threadIdx.x;
    float4 f = ((const float4*)x)[i];
    uint32_t l0, l1;
    uint32_t h0 = pack2(f.x, f.y, l0);
    uint32_t h1 = pack2(f.z, f.w, l1);
    *(uint2*)(g_xh + 4 * i) = make_uint2(h0, h1);
    *(uint2*)(g_xl + 4 * i) = make_uint2(l0, l1);
}
__global__ void k_prep_w(const float* __restrict__ w_qkv)
{
    int i = blockIdx.x * 256 + threadIdx.x;
    float v = w_qkv[CC * CC + i];
    __nv_bfloat16 h = __float2bfloat16(v);
    g_Wkh[i] = h;
    g_Wkl[i] = __float2bfloat16(v - __bfloat162float(h));
}

// ---------------- fp32 64x64 core for small middle GEMMs ----------------
template<bool BSCALE>
__device__ __forceinline__ void core64(
    const float* __restrict__ A, int lda,
    const float* __restrict__ B, int ldb,
    const float* __restrict__ bscale, float acc[4][4])
{
    __shared__ __align__(16) float As[16][68];
    __shared__ __align__(16) float Bs[16][68];
    const int t = threadIdx.x, tx = t & 15, ty = t >> 4;

    for (int k0 = 0; k0 < CC; k0 += 16) {
        __syncthreads();
        {
            const int r = t >> 2, q = t & 3;
            float4 a4 = *(const float4*)(A + (size_t)r * lda + k0 + 4 * q);
            As[4*q+0][r] = a4.x; As[4*q+1][r] = a4.y; As[4*q+2][r] = a4.z; As[4*q+3][r] = a4.w;
            const int kr = t >> 4, c0 = (t & 15) * 4;
            float4 b4 = *(const float4*)(B + (size_t)(k0 + kr) * ldb + c0);
            if (BSCALE) {
                float s = 1.0f / bscale[k0 + kr];
                b4.x *= s; b4.y *= s; b4.z *= s; b4.w *= s;
            }
            *(float4*)&Bs[kr][c0] = b4;
        }
        __syncthreads();
        #pragma unroll
        for (int k = 0; k < 16; k++) {
            float4 a4 = *(const float4*)&As[k][ty * 4];
            float4 b4 = *(const float4*)&Bs[k][tx * 4];
            float av[4] = {a4.x, a4.y, a4.z, a4.w};
            float bv[4] = {b4.x, b4.y, b4.z, b4.w};
            #pragma unroll
            for (int i = 0; i < 4; i++)
                #pragma unroll
                for (int j = 0; j < 4; j++)
                    acc[i][j] += av[i] * bv[j];
        }
    }
}

__global__ void __launch_bounds__(256)
k_w2(const float* __restrict__ w_proj, const float* __restrict__ w_qkv)
{
    const int m0 = blockIdx.y * 64, n0 = blockIdx.x * 64;
    float acc[4][4] = {};
    core64<false>(w_proj + (size_t)m0 * CC, CC,
                  w_qkv + (size_t)2 * CC * CC + n0, CC, nullptr, acc);
    const int tx = threadIdx.x & 15, ty = threadIdx.x >> 4;
    #pragma unroll
    for (int i = 0; i < 4; i++)
        #pragma unroll
        for (int j = 0; j < 4; j++)
            g_W2[(m0 + ty * 4 + i) * CC + n0 + tx * 4 + j] = acc[i][j];
}

__global__ void __launch_bounds__(256)
k_r(const float* __restrict__ w_qkv)
{
    const int b = blockIdx.z, m0 = blockIdx.y * 64, n0 = blockIdx.x * 64;
    float acc[4][4] = {};
    core64<true>(g_St + (size_t)b * CC * CC + (size_t)m0 * CC, CC,
                 w_qkv + n0, CC, g_rowsum + b * CC, acc);
    const int tx = threadIdx.x & 15, ty = threadIdx.x >> 4;
    float* Rb = g_R + (size_t)b * CC * CC;
    #pragma unroll
    for (int i = 0; i < 4; i++)
        #pragma unroll
        for (int j = 0; j < 4; j++)
            Rb[(m0 + ty * 4 + i) * CC + n0 + tx * 4 + j] = acc[i][j];
}

__global__ void __launch_bounds__(256)
k_m(const float* __restrict__ gamma, const float* __restrict__ var)
{
    const int b = blockIdx.z, m0 = blockIdx.y * 64, n0 = blockIdx.x * 64;
    float acc[4][4] = {};
    core64<false>(g_W2 + (size_t)m0 * CC, CC,
                  g_R + (size_t)b * CC * CC + n0, CC, nullptr, acc);
    const int tx = threadIdx.x & 15, ty = threadIdx.x >> 4;
    __nv_bfloat16* Mh = g_Mh + (size_t)b * CC * CC;
    __nv_bfloat16* Ml = g_Ml + (size_t)b * CC * CC;
    #pragma unroll
    for (int i = 0; i < 4; i++) {
        const int o = m0 + ty * 4 + i;
        const float inv = gamma[o] * rsqrtf(var[o] + EPS);
        #pragma unroll
        for (int j = 0; j < 4; j++) {
            float v = inv * acc[i][j];
            __nv_bfloat16 h = __float2bfloat16(v);
            Mh[o * CC + n0 + tx * 4 + j] = h;
            Ml[o * CC + n0 + tx * 4 + j] = __float2bfloat16(v - __bfloat162float(h));
        }
    }
}

// ---------------- launch ----------------
extern "C" void kernel_launch(void* const* d_in, const int* in_sizes, int n_in,
                              void* d_out, int out_size)
{
    const float* x      = (const float*)d_in[0];
    const float* w_qkv  = (const float*)d_in[1];
    const float* w_proj = (const float*)d_in[2];
    const float* gamma  = (const float*)d_in[3];
    const float* beta   = (const float*)d_in[4];
    const float* mean   = (const float*)d_in[5];
    const float* var    = (const float*)d_in[6];
    float* out = (float*)d_out;

    cudaFuncSetAttribute(k_exp, cudaFuncAttributeMaxDynamicSharedMemorySize, NN_SMEM);
    cudaFuncSetAttribute(k_out, cudaFuncAttributeMaxDynamicSharedMemorySize, NN_SMEM);
    cudaFuncSetAttribute(k_st,  cudaFuncAttributeMaxDynamicSharedMemorySize, NT_SMEM);

    void* p_rowsum = nullptr;
    cudaGetSymbolAddress(&p_rowsum, g_rowsum);
    cudaMemsetAsync(p_rowsum, 0, (size_t)BB * CC * sizeof(float));

    dim3 blk(256);
    k_prep_x<<<dim3((size_t)BB * CC * NSP / 1024), blk>>>(x);
    k_prep_w<<<dim3(CC * CC / 256), blk>>>(w_qkv);
    k_w2<<<dim3(4, 4), blk>>>(w_proj, w_qkv);
    k_exp<<<dim3(NSP / 256, 2, BB), blk, NN_SMEM>>>();
    k_st<<<dim3(1, 2, BB * KSPLIT), blk, NT_SMEM>>>();
    k_sum<<<dim3(BB * CC * CC / 1024), blk>>>();
    k_r<<<dim3(4, 4, BB), blk>>>(w_qkv);
    k_m<<<dim3(4, 4, BB), blk>>>(gamma, var);
    k_out<<<dim3(NSP / 256, 2, BB), blk, NN_SMEM>>>(gamma, beta, mean, var, out);
}

// round 10
// speedup vs baseline: 1.0049x; 1.0049x over previous
#include <cuda_runtime.h>
#include <cuda_bf16.h>
#include <math.h>
#include <stdint.h>

#define CC   256
#define NSP  16384
#define BB   8
#define EPS  1e-5f
#define KSPLIT 8

// ---------------- scratch (device globals) ----------------
__device__ __nv_bfloat16 g_xh[(size_t)BB * CC * NSP], g_xl[(size_t)BB * CC * NSP];
__device__ __nv_bfloat16 g_Eh[(size_t)BB * CC * NSP], g_El[(size_t)BB * CC * NSP];
__device__ float g_rowsum[BB * CC];
__device__ float g_Stp[(size_t)KSPLIT * BB * CC * CC];
__device__ float g_St[BB * CC * CC];
__device__ float g_R[BB * CC * CC];
__device__ float g_W2[CC * CC];
__device__ __nv_bfloat16 g_Wkh[CC * CC], g_Wkl[CC * CC];
__device__ __nv_bfloat16 g_Mh[BB * CC * CC], g_Ml[BB * CC * CC];

// ---------------- smem stage layouts (1 CTA/SM, 3-stage rings) --------------
// NN (k_exp/k_out): A [128][40] hi/lo + B(x^T) [32][264] hi/lo
#define NN_AH 0
#define NN_AL 10240
#define NN_BH 20480
#define NN_BL 37376
#define NN_STG 54272
#define NN_SMEM (3 * NN_STG)     // 162816
// NT (k_st): A [128][40] hi/lo + B [256][40] hi/lo
#define NT_AH 0
#define NT_AL 10240
#define NT_BH 20480
#define NT_BL 40960
#define NT_STG 61440
#define NT_SMEM (3 * NT_STG)     // 184320

// ---------------- helpers ----------------
__device__ __forceinline__ uint32_t smem_u32(const void* p) {
    uint32_t a;
    asm("{ .reg .u64 t; cvta.to.shared.u64 t, %1; cvt.u32.u64 %0, t; }" : "=r"(a) : "l"(p));
    return a;
}
__device__ __forceinline__ void cpa16(uint32_t dst, const void* src) {
    asm volatile("cp.async.cg.shared.global [%0], [%1], 16;" :: "r"(dst), "l"(src));
}
#define CP_COMMIT()  asm volatile("cp.async.commit_group;")
#define CP_WAIT(n)   asm volatile("cp.async.wait_group %0;" :: "n"(n))

__device__ __forceinline__ void ldm4(uint32_t* r, const void* p) {
    uint32_t a = (uint32_t)__cvta_generic_to_shared(p);
    asm volatile("ldmatrix.sync.aligned.m8n8.x4.shared.b16 {%0,%1,%2,%3},[%4];"
                 : "=r"(r[0]), "=r"(r[1]), "=r"(r[2]), "=r"(r[3]) : "r"(a));
}
__device__ __forceinline__ void ldm2(uint32_t* r, const void* p) {
    uint32_t a = (uint32_t)__cvta_generic_to_shared(p);
    asm volatile("ldmatrix.sync.aligned.m8n8.x2.shared.b16 {%0,%1},[%2];"
                 : "=r"(r[0]), "=r"(r[1]) : "r"(a));
}
__device__ __forceinline__ void ldm2t(uint32_t* r, const void* p) {
    uint32_t a = (uint32_t)__cvta_generic_to_shared(p);
    asm volatile("ldmatrix.sync.aligned.m8n8.x2.trans.shared.b16 {%0,%1},[%2];"
                 : "=r"(r[0]), "=r"(r[1]) : "r"(a));
}
__device__ __forceinline__ void mma_bf(float* d, const uint32_t* a, const uint32_t* b) {
    asm volatile("mma.sync.aligned.m16n8k16.row.col.f32.bf16.bf16.f32 "
                 "{%0,%1,%2,%3},{%4,%5,%6,%7},{%8,%9},{%0,%1,%2,%3};"
                 : "+f"(d[0]), "+f"(d[1]), "+f"(d[2]), "+f"(d[3])
                 : "r"(a[0]), "r"(a[1]), "r"(a[2]), "r"(a[3]), "r"(b[0]), "r"(b[1]));
}
__device__ __forceinline__ uint32_t pack2(float a, float b, uint32_t& lo) {
    __nv_bfloat16 ha = __float2bfloat16(a), hb = __float2bfloat16(b);
    __nv_bfloat16 la = __float2bfloat16(a - __bfloat162float(ha));
    __nv_bfloat16 lb = __float2bfloat16(b - __bfloat162float(hb));
    lo = (uint32_t)__bfloat16_as_ushort(la) | ((uint32_t)__bfloat16_as_ushort(lb) << 16);
    return (uint32_t)__bfloat16_as_ushort(ha) | ((uint32_t)__bfloat16_as_ushort(hb) << 16);
}

// ---------------- staging (cp.async pure copies) ----------------
// A: 128 rows x 32 k, smem [128][40]
__device__ __forceinline__ void stageR(uint32_t dh, uint32_t dl,
    const __nv_bfloat16* __restrict__ gh, const __nv_bfloat16* __restrict__ gl,
    size_t stride)
{
    const int r = threadIdx.x >> 1, p = threadIdx.x & 1;
    const char* s0 = (const char*)(gh + (size_t)r * stride) + p * 32;
    const char* s1 = (const char*)(gl + (size_t)r * stride) + p * 32;
    const uint32_t o = r * 80 + p * 32;
    cpa16(dh + o, s0); cpa16(dh + o + 16, s0 + 16);
    cpa16(dl + o, s1); cpa16(dl + o + 16, s1 + 16);
}
// B(NN): 32 k-rows x 256 n, smem [32][264]
__device__ __forceinline__ void stageB256(uint32_t dh, uint32_t dl,
    const __nv_bfloat16* __restrict__ gh, const __nv_bfloat16* __restrict__ gl)
{
    const int t = threadIdx.x;
    #pragma unroll
    for (int it = 0; it < 2; it++) {
        const int k = (t >> 4) + it * 16, seg = t & 15;
        const char* s0 = (const char*)(gh + (size_t)k * NSP) + seg * 32;
        const char* s1 = (const char*)(gl + (size_t)k * NSP) + seg * 32;
        const uint32_t o = k * 528 + seg * 32;
        cpa16(dh + o, s0); cpa16(dh + o + 16, s0 + 16);
        cpa16(dl + o, s1); cpa16(dl + o + 16, s1 + 16);
    }
}
// B(NT): 256 rows x 32 k, smem [256][40]
__device__ __forceinline__ void stageR256(uint32_t dh, uint32_t dl,
    const __nv_bfloat16* __restrict__ gh, const __nv_bfloat16* __restrict__ gl)
{
    const int r = threadIdx.x;
    const char* s0 = (const char*)(gh + (size_t)r * NSP);
    const char* s1 = (const char*)(gl + (size_t)r * NSP);
    const uint32_t o = r * 80;
    cpa16(dh + o, s0);      cpa16(dh + o + 16, s0 + 16);
    cpa16(dh + o + 32, s0 + 32); cpa16(dh + o + 48, s0 + 48);
    cpa16(dl + o, s1);      cpa16(dl + o + 16, s1 + 16);
    cpa16(dl + o + 32, s1 + 32); cpa16(dl + o + 48, s1 + 48);
}

// ---- 64x64 warp-tile compute, single live A-frag set (low reg pressure) ----
template<bool BT>
__device__ __forceinline__ void computeW(const char* smb, float acc[4][8][4])
{
    const int t = threadIdx.x, lane = t & 31, w = t >> 5;
    const int wm = w & 1, wn = w >> 1;            // wm 0..1 (64 rows), wn 0..3 (64 cols)
    const int ar = wm * 64 + (lane & 15);
    const int ac = (lane >> 4) * 8;
    const int btr = lane & 15;
    const int btc = wn * 64;
    const int nrb = wn * 64 + (lane & 7);
    const int nc  = ((lane >> 3) & 1) * 8;

    const __nv_bfloat16* Ah = (const __nv_bfloat16*)(smb + NN_AH);
    const __nv_bfloat16* Al = (const __nv_bfloat16*)(smb + NN_AL);
    const __nv_bfloat16* Bh = (const __nv_bfloat16*)(smb + NN_BH);
    const __nv_bfloat16* Bl = (const __nv_bfloat16*)(smb + (BT ? NN_BL : NT_BL));

    #pragma unroll
    for (int kk = 0; kk < 2; kk++) {
        uint32_t af[4][4];
        // ---- phase 1: af = Ah fragments; Ah*Bh then Ah*Bl ----
        #pragma unroll
        for (int mi = 0; mi < 4; mi++)
            ldm4(af[mi], Ah + (ar + mi * 16) * 40 + kk * 16 + ac);
        #pragma unroll
        for (int nh = 0; nh < 2; nh++) {
            uint32_t bq[4][2];
            #pragma unroll
            for (int ni = 0; ni < 4; ni++) {
                if (BT) ldm2t(bq[ni], Bh + (kk * 16 + btr) * 264 + btc + nh * 32 + ni * 8);
                else    ldm2 (bq[ni], Bh + (nrb + nh * 32 + ni * 8) * 40 + kk * 16 + nc);
            }
            #pragma unroll
            for (int mi = 0; mi < 4; mi++)
                #pragma unroll
                for (int ni = 0; ni < 4; ni++)
                    mma_bf(acc[mi][nh * 4 + ni], af[mi], bq[ni]);
            #pragma unroll
            for (int ni = 0; ni < 4; ni++) {
                if (BT) ldm2t(bq[ni], Bl + (kk * 16 + btr) * 264 + btc + nh * 32 + ni * 8);
                else    ldm2 (bq[ni], Bl + (nrb + nh * 32 + ni * 8) * 40 + kk * 16 + nc);
            }
            #pragma unroll
            for (int mi = 0; mi < 4; mi++)
                #pragma unroll
                for (int ni = 0; ni < 4; ni++)
                    mma_bf(acc[mi][nh * 4 + ni], af[mi], bq[ni]);
        }
        // ---- phase 2: af = Al fragments (overwrite); Al*Bh (Bh reloaded) ----
        #pragma unroll
        for (int mi = 0; mi < 4; mi++)
            ldm4(af[mi], Al + (ar + mi * 16) * 40 + kk * 16 + ac);
        #pragma unroll
        for (int nh = 0; nh < 2; nh++) {
            uint32_t bq[4][2];
            #pragma unroll
            for (int ni = 0; ni < 4; ni++) {
                if (BT) ldm2t(bq[ni], Bh + (kk * 16 + btr) * 264 + btc + nh * 32 + ni * 8);
                else    ldm2 (bq[ni], Bh + (nrb + nh * 32 + ni * 8) * 40 + kk * 16 + nc);
            }
            #pragma unroll
            for (int mi = 0; mi < 4; mi++)
                #pragma unroll
                for (int ni = 0; ni < 4; ni++)
                    mma_bf(acc[mi][nh * 4 + ni], af[mi], bq[ni]);
        }
    }
}

#define ACC_ZERO8(acc) { \
    _Pragma("unroll") for (int _a = 0; _a < 4; _a++) \
    _Pragma("unroll") for (int _c = 0; _c < 8; _c++) \
    _Pragma("unroll") for (int _d = 0; _d < 4; _d++) acc[_a][_c][_d] = 0.f; }

// 3-stage, 1-sync mainloop for NN kernels (8 chunks of K=32)
#define NN_MAINLOOP(Agh, Agl, Bgh, Bgl) { \
    stageR(sb + NN_AH, sb + NN_AL, Agh, Agl, CC); \
    stageB256(sb + NN_BH, sb + NN_BL, Bgh, Bgl); \
    CP_COMMIT(); \
    stageR(sb + NN_STG + NN_AH, sb + NN_STG + NN_AL, Agh + 32, Agl + 32, CC); \
    stageB256(sb + NN_STG + NN_BH, sb + NN_STG + NN_BL, \
              Bgh + (size_t)32 * NSP, Bgl + (size_t)32 * NSP); \
    CP_COMMIT(); \
    _Pragma("unroll 1") \
    for (int ch = 0; ch < 8; ch++) { \
        if (ch < 7) { CP_WAIT(1); } else { CP_WAIT(0); } \
        __syncthreads(); \
        if (ch + 2 < 8) { \
            const int kn = (ch + 2) * 32; \
            const uint32_t bb = sb + ((ch + 2) % 3) * NN_STG; \
            stageR(bb + NN_AH, bb + NN_AL, Agh + kn, Agl + kn, CC); \
            stageB256(bb + NN_BH, bb + NN_BL, \
                      Bgh + (size_t)kn * NSP, Bgl + (size_t)kn * NSP); \
            CP_COMMIT(); \
        } \
        computeW<true>(sm + (ch % 3) * NN_STG, acc); \
    } }

// ---------------- K1: E = exp(Wk @ x) + rowsums ----------------
__global__ void __launch_bounds__(256, 1)
k_exp()
{
    extern __shared__ char sm[];
    const uint32_t sb = smem_u32(sm);
    const int b = blockIdx.z, m0 = blockIdx.y * 128, n0 = blockIdx.x * 256;

    const __nv_bfloat16* Agh = g_Wkh + (size_t)m0 * CC;
    const __nv_bfloat16* Agl = g_Wkl + (size_t)m0 * CC;
    const __nv_bfloat16* Bgh = g_xh + (size_t)b * CC * NSP + n0;
    const __nv_bfloat16* Bgl = g_xl + (size_t)b * CC * NSP + n0;

    float acc[4][8][4]; ACC_ZERO8(acc);
    NN_MAINLOOP(Agh, Agl, Bgh, Bgl);

    const int t = threadIdx.x, lane = t & 31, w = t >> 5;
    const int wm = w & 1, wn = w >> 1;
    const int rbase = m0 + wm * 64 + (lane >> 2);
    const int cbase = n0 + wn * 64 + (lane & 3) * 2;
    __nv_bfloat16* Eh = g_Eh + (size_t)b * CC * NSP;
    __nv_bfloat16* El = g_El + (size_t)b * CC * NSP;

    float rs[8] = {0, 0, 0, 0, 0, 0, 0, 0};
    #pragma unroll
    for (int mi = 0; mi < 4; mi++)
        #pragma unroll
        for (int h = 0; h < 2; h++) {
            const int rr = rbase + mi * 16 + 8 * h;
            #pragma unroll
            for (int ni = 0; ni < 8; ni++) {
                float e0 = __expf(acc[mi][ni][2 * h + 0]);
                float e1 = __expf(acc[mi][ni][2 * h + 1]);
                rs[mi * 2 + h] += e0 + e1;
                uint32_t lp, hp = pack2(e0, e1, lp);
                const size_t off = (size_t)rr * NSP + cbase + ni * 8;
                *(uint32_t*)(Eh + off) = hp;
                *(uint32_t*)(El + off) = lp;
            }
        }
    #pragma unroll
    for (int i = 0; i < 8; i++) {
        float v = rs[i];
        v += __shfl_xor_sync(0xffffffffu, v, 1);
        v += __shfl_xor_sync(0xffffffffu, v, 2);
        if ((lane & 3) == 0) {
            const int rr = rbase + (i >> 1) * 16 + 8 * (i & 1);
            atomicAdd(&g_rowsum[b * CC + rr], v);
        }
    }
}

// ---------------- K5: out = relu(M @ x + bias) ----------------
__global__ void __launch_bounds__(256, 1)
k_out(const float* __restrict__ gamma, const float* __restrict__ beta,
      const float* __restrict__ mean,  const float* __restrict__ var,
      float* __restrict__ out)
{
    extern __shared__ char sm[];
    const uint32_t sb = smem_u32(sm);
    const int b = blockIdx.z, m0 = blockIdx.y * 128, n0 = blockIdx.x * 256;

    const __nv_bfloat16* Agh = g_Mh + (size_t)b * CC * CC + (size_t)m0 * CC;
    const __nv_bfloat16* Agl = g_Ml + (size_t)b * CC * CC + (size_t)m0 * CC;
    const __nv_bfloat16* Bgh = g_xh + (size_t)b * CC * NSP + n0;
    const __nv_bfloat16* Bgl = g_xl + (size_t)b * CC * NSP + n0;

    float acc[4][8][4]; ACC_ZERO8(acc);
    NN_MAINLOOP(Agh, Agl, Bgh, Bgl);

    const int t = threadIdx.x, lane = t & 31, w = t >> 5;
    const int wm = w & 1, wn = w >> 1;
    const int rbase = m0 + wm * 64 + (lane >> 2);
    const int cbase = n0 + wn * 64 + (lane & 3) * 2;
    float* Ob = out + (size_t)b * CC * NSP;

    #pragma unroll
    for (int mi = 0; mi < 4; mi++)
        #pragma unroll
        for (int h = 0; h < 2; h++) {
            const int o = rbase + mi * 16 + 8 * h;
            const float inv  = gamma[o] * rsqrtf(var[o] + EPS);
            const float bias = beta[o] - mean[o] * inv;
            #pragma unroll
            for (int ni = 0; ni < 8; ni++) {
                float2 v;
                v.x = fmaxf(acc[mi][ni][2 * h + 0] + bias, 0.f);
                v.y = fmaxf(acc[mi][ni][2 * h + 1] + bias, 0.f);
                *(float2*)(Ob + (size_t)o * NSP + cbase + ni * 8) = v;
            }
        }
}

// ---------------- K2: St partial slabs (atomic-free, 3-stage) ---------------
__global__ void __launch_bounds__(256, 1)
k_st()
{
    extern __shared__ char sm[];
    const uint32_t sb = smem_u32(sm);
    const int e0 = blockIdx.y * 128;
    const int b = blockIdx.z >> 3, ks = blockIdx.z & 7;
    const int kbeg = ks * (NSP / KSPLIT);   // 2048
    const int NCH = (NSP / KSPLIT) / 32;    // 64

    const __nv_bfloat16* Agh = g_xh + (size_t)(b * CC + e0) * NSP + kbeg;
    const __nv_bfloat16* Agl = g_xl + (size_t)(b * CC + e0) * NSP + kbeg;
    const __nv_bfloat16* Bgh = g_Eh + (size_t)b * CC * NSP + kbeg;
    const __nv_bfloat16* Bgl = g_El + (size_t)b * CC * NSP + kbeg;

    float acc[4][8][4]; ACC_ZERO8(acc);

    stageR(sb + NT_AH, sb + NT_AL, Agh, Agl, NSP);
    stageR256(sb + NT_BH, sb + NT_BL, Bgh, Bgl);
    CP_COMMIT();
    stageR(sb + NT_STG + NT_AH, sb + NT_STG + NT_AL, Agh + 32, Agl + 32, NSP);
    stageR256(sb + NT_STG + NT_BH, sb + NT_STG + NT_BL, Bgh + 32, Bgl + 32);
    CP_COMMIT();
    #pragma unroll 1
    for (int ch = 0; ch < NCH; ch++) {
        if (ch + 1 < NCH) { CP_WAIT(1); } else { CP_WAIT(0); }
        __syncthreads();
        if (ch + 2 < NCH) {
            const int kn = (ch + 2) * 32;
            const uint32_t bb = sb + ((ch + 2) % 3) * NT_STG;
            stageR(bb + NT_AH, bb + NT_AL, Agh + kn, Agl + kn, NSP);
            stageR256(bb + NT_BH, bb + NT_BL, Bgh + kn, Bgl + kn);
            CP_COMMIT();
        }
        computeW<false>(sm + (ch % 3) * NT_STG, acc);
    }

    const int t = threadIdx.x, lane = t & 31, w = t >> 5;
    const int wm = w & 1, wn = w >> 1;
    const int rbase = e0 + wm * 64 + (lane >> 2);
    const int cbase = wn * 64 + (lane & 3) * 2;
    float* Sp = g_Stp + ((size_t)ks * BB + b) * CC * CC;

    #pragma unroll
    for (int mi = 0; mi < 4; mi++)
        #pragma unroll
        for (int h = 0; h < 2; h++) {
            const int rr = rbase + mi * 16 + 8 * h;
            #pragma unroll
            for (int ni = 0; ni < 8; ni++) {
                float2 v;
                v.x = acc[mi][ni][2 * h + 0];
                v.y = acc[mi][ni][2 * h + 1];
                *(float2*)(Sp + (size_t)rr * CC + cbase + ni * 8) = v;
            }
        }
}

// ---------------- reduce slabs (float4) ----------------
__global__ void k_sum()
{
    const size_t i = ((size_t)blockIdx.x * 256 + threadIdx.x) * 4;
    const size_t STRIDE = (size_t)BB * CC * CC;
    float4 s = make_float4(0.f, 0.f, 0.f, 0.f);
    #pragma unroll
    for (int ks = 0; ks < KSPLIT; ks++) {
        float4 v = *(const float4*)(g_Stp + ks * STRIDE + i);
        s.x += v.x; s.y += v.y; s.z += v.z; s.w += v.w;
    }
    *(float4*)(g_St + i) = s;
}

// ---------------- prep: split x and Wk to bf16 hi/lo ----------------
__global__ void k_prep_x(const float* __restrict__ x)
{
    const size_t i = (size_t)blockIdx.x * 256 + threadIdx.x;
    float4 f = ((const float4*)x)[i];
    uint32_t l0, l1;
    uint32_t h0 = pack2(f.x, f.y, l0);
    uint32_t h1 = pack2(f.z, f.w, l1);
    *(uint2*)(g_xh + 4 * i) = make_uint2(h0, h1);
    *(uint2*)(g_xl + 4 * i) = make_uint2(l0, l1);
}
__global__ void k_prep_w(const float* __restrict__ w_qkv)
{
    int i = blockIdx.x * 256 + threadIdx.x;
    float v = w_qkv[CC * CC + i];
    __nv_bfloat16 h = __float2bfloat16(v);
    g_Wkh[i] = h;
    g_Wkl[i] = __float2bfloat16(v - __bfloat162float(h));
}

// ---------------- fp32 64x64 core for small middle GEMMs ----------------
template<bool BSCALE>
__device__ __forceinline__ void core64(
    const float* __restrict__ A, int lda,
    const float* __restrict__ B, int ldb,
    const float* __restrict__ bscale, float acc[4][4])
{
    __shared__ __align__(16) float As[16][68];
    __shared__ __align__(16) float Bs[16][68];
    const int t = threadIdx.x, tx = t & 15, ty = t >> 4;

    for (int k0 = 0; k0 < CC; k0 += 16) {
        __syncthreads();
        {
            const int r = t >> 2, q = t & 3;
            float4 a4 = *(const float4*)(A + (size_t)r * lda + k0 + 4 * q);
            As[4*q+0][r] = a4.x; As[4*q+1][r] = a4.y; As[4*q+2][r] = a4.z; As[4*q+3][r] = a4.w;
            const int kr = t >> 4, c0 = (t & 15) * 4;
            float4 b4 = *(const float4*)(B + (size_t)(k0 + kr) * ldb + c0);
            if (BSCALE) {
                float s = 1.0f / bscale[k0 + kr];
                b4.x *= s; b4.y *= s; b4.z *= s; b4.w *= s;
            }
            *(float4*)&Bs[kr][c0] = b4;
        }
        __syncthreads();
        #pragma unroll
        for (int k = 0; k < 16; k++) {
            float4 a4 = *(const float4*)&As[k][ty * 4];
            float4 b4 = *(const float4*)&Bs[k][tx * 4];
            float av[4] = {a4.x, a4.y, a4.z, a4.w};
            float bv[4] = {b4.x, b4.y, b4.z, b4.w};
            #pragma unroll
            for (int i = 0; i < 4; i++)
                #pragma unroll
                for (int j = 0; j < 4; j++)
                    acc[i][j] += av[i] * bv[j];
        }
    }
}

__global__ void __launch_bounds__(256)
k_w2(const float* __restrict__ w_proj, const float* __restrict__ w_qkv)
{
    const int m0 = blockIdx.y * 64, n0 = blockIdx.x * 64;
    float acc[4][4] = {};
    core64<false>(w_proj + (size_t)m0 * CC, CC,
                  w_qkv + (size_t)2 * CC * CC + n0, CC, nullptr, acc);
    const int tx = threadIdx.x & 15, ty = threadIdx.x >> 4;
    #pragma unroll
    for (int i = 0; i < 4; i++)
        #pragma unroll
        for (int j = 0; j < 4; j++)
            g_W2[(m0 + ty * 4 + i) * CC + n0 + tx * 4 + j] = acc[i][j];
}

__global__ void __launch_bounds__(256)
k_r(const float* __restrict__ w_qkv)
{
    const int b = blockIdx.z, m0 = blockIdx.y * 64, n0 = blockIdx.x * 64;
    float acc[4][4] = {};
    core64<true>(g_St + (size_t)b * CC * CC + (size_t)m0 * CC, CC,
                 w_qkv + n0, CC, g_rowsum + b * CC, acc);
    const int tx = threadIdx.x & 15, ty = threadIdx.x >> 4;
    float* Rb = g_R + (size_t)b * CC * CC;
    #pragma unroll
    for (int i = 0; i < 4; i++)
        #pragma unroll
        for (int j = 0; j < 4; j++)
            Rb[(m0 + ty * 4 + i) * CC + n0 + tx * 4 + j] = acc[i][j];
}

__global__ void __launch_bounds__(256)
k_m(const float* __restrict__ gamma, const float* __restrict__ var)
{
    const int b = blockIdx.z, m0 = blockIdx.y * 64, n0 = blockIdx.x * 64;
    float acc[4][4] = {};
    core64<false>(g_W2 + (size_t)m0 * CC, CC,
                  g_R + (size_t)b * CC * CC + n0, CC, nullptr, acc);
    const int tx = threadIdx.x & 15, ty = threadIdx.x >> 4;
    __nv_bfloat16* Mh = g_Mh + (size_t)b * CC * CC;
    __nv_bfloat16* Ml = g_Ml + (size_t)b * CC * CC;
    #pragma unroll
    for (int i = 0; i < 4; i++) {
        const int o = m0 + ty * 4 + i;
        const float inv = gamma[o] * rsqrtf(var[o] + EPS);
        #pragma unroll
        for (int j = 0; j < 4; j++) {
            float v = inv * acc[i][j];
            __nv_bfloat16 h = __float2bfloat16(v);
            Mh[o * CC + n0 + tx * 4 + j] = h;
            Ml[o * CC + n0 + tx * 4 + j] = __float2bfloat16(v - __bfloat162float(h));
        }
    }
}

// ---------------- launch ----------------
extern "C" void kernel_launch(void* const* d_in, const int* in_sizes, int n_in,
                              void* d_out, int out_size)
{
    const float* x      = (const float*)d_in[0];
    const float* w_qkv  = (const float*)d_in[1];
    const float* w_proj = (const float*)d_in[2];
    const float* gamma  = (const float*)d_in[3];
    const float* beta   = (const float*)d_in[4];
    const float* mean   = (const float*)d_in[5];
    const float* var    = (const float*)d_in[6];
    float* out = (float*)d_out;

    cudaFuncSetAttribute(k_exp, cudaFuncAttributeMaxDynamicSharedMemorySize, NN_SMEM);
    cudaFuncSetAttribute(k_out, cudaFuncAttributeMaxDynamicSharedMemorySize, NN_SMEM);
    cudaFuncSetAttribute(k_st,  cudaFuncAttributeMaxDynamicSharedMemorySize, NT_SMEM);

    void* p_rowsum = nullptr;
    cudaGetSymbolAddress(&p_rowsum, g_rowsum);
    cudaMemsetAsync(p_rowsum, 0, (size_t)BB * CC * sizeof(float));

    dim3 blk(256);
    k_prep_x<<<dim3((size_t)BB * CC * NSP / 1024), blk>>>(x);
    k_prep_w<<<dim3(CC * CC / 256), blk>>>(w_qkv);
    k_w2<<<dim3(4, 4), blk>>>(w_proj, w_qkv);
    k_exp<<<dim3(NSP / 256, 2, BB), blk, NN_SMEM>>>();
    k_st<<<dim3(1, 2, BB * KSPLIT), blk, NT_SMEM>>>();
    k_sum<<<dim3(BB * CC * CC / 1024), blk>>>();
    k_r<<<dim3(4, 4, BB), blk>>>(w_qkv);
    k_m<<<dim3(4, 4, BB), blk>>>(gamma, var);
    k_out<<<dim3(NSP / 256, 2, BB), blk, NN_SMEM>>>(gamma, beta, mean, var, out);
}

// round 13
// speedup vs baseline: 1.0810x; 1.0757x over previous
#include <cuda_runtime.h>
#include <cuda_bf16.h>
#include <math.h>
#include <stdint.h>

#define CC   256
#define NSP  16384
#define BB   8
#define EPS  1e-5f
#define KSPLIT 8

// ---------------- scratch (device globals) ----------------
__device__ __nv_bfloat16 g_xh[(size_t)BB * CC * NSP], g_xl[(size_t)BB * CC * NSP];
__device__ __nv_bfloat16 g_Eh[(size_t)BB * CC * NSP], g_El[(size_t)BB * CC * NSP];
__device__ float g_rowsum[BB * CC];
__device__ float g_Stp[(size_t)KSPLIT * BB * CC * CC];
__device__ float g_St[BB * CC * CC];
__device__ float g_R[BB * CC * CC];
__device__ float g_W2[CC * CC];
__device__ __nv_bfloat16 g_Wkh[CC * CC], g_Wkl[CC * CC];
__device__ __nv_bfloat16 g_Mh[BB * CC * CC], g_Ml[BB * CC * CC];

// ---------------- smem stage layouts ----------------
// NN kernels (k_exp/k_out): A [128][40] hi/lo + B(x^T) [32][136] hi/lo, 3-stage
#define NN_AH 0
#define NN_AL 10240
#define NN_BH 20480
#define NN_BL 29184
#define NN_STG 37888
#define NN_SMEM (3 * NN_STG)    // 113664 -> 2 CTAs/SM = 227328
// NT kernel (k_st): A,B both [128][40] hi/lo, 2-stage
#define NT_AH 0
#define NT_AL 10240
#define NT_BH 20480
#define NT_BL 30720
#define NT_STG 40960
#define NT_SMEM (2 * NT_STG)    // 81920 -> 2 CTAs/SM

// ---------------- helpers ----------------
__device__ __forceinline__ uint32_t smem_u32(const void* p) {
    uint32_t a;
    asm("{ .reg .u64 t; cvta.to.shared.u64 t, %1; cvt.u32.u64 %0, t; }" : "=r"(a) : "l"(p));
    return a;
}
__device__ __forceinline__ void cpa16(uint32_t dst, const void* src) {
    asm volatile("cp.async.cg.shared.global [%0], [%1], 16;" :: "r"(dst), "l"(src));
}
#define CP_COMMIT()  asm volatile("cp.async.commit_group;")
#define CP_WAIT(n)   asm volatile("cp.async.wait_group %0;" :: "n"(n))

__device__ __forceinline__ void ldm4(uint32_t* r, const void* p) {
    uint32_t a = (uint32_t)__cvta_generic_to_shared(p);
    asm volatile("ldmatrix.sync.aligned.m8n8.x4.shared.b16 {%0,%1,%2,%3},[%4];"
                 : "=r"(r[0]), "=r"(r[1]), "=r"(r[2]), "=r"(r[3]) : "r"(a));
}
__device__ __forceinline__ void ldm2(uint32_t* r, const void* p) {
    uint32_t a = (uint32_t)__cvta_generic_to_shared(p);
    asm volatile("ldmatrix.sync.aligned.m8n8.x2.shared.b16 {%0,%1},[%2];"
                 : "=r"(r[0]), "=r"(r[1]) : "r"(a));
}
__device__ __forceinline__ void ldm2t(uint32_t* r, const void* p) {
    uint32_t a = (uint32_t)__cvta_generic_to_shared(p);
    asm volatile("ldmatrix.sync.aligned.m8n8.x2.trans.shared.b16 {%0,%1},[%2];"
                 : "=r"(r[0]), "=r"(r[1]) : "r"(a));
}
__device__ __forceinline__ void mma_bf(float* d, const uint32_t* a, const uint32_t* b) {
    asm volatile("mma.sync.aligned.m16n8k16.row.col.f32.bf16.bf16.f32 "
                 "{%0,%1,%2,%3},{%4,%5,%6,%7},{%8,%9},{%0,%1,%2,%3};"
                 : "+f"(d[0]), "+f"(d[1]), "+f"(d[2]), "+f"(d[3])
                 : "r"(a[0]), "r"(a[1]), "r"(a[2]), "r"(a[3]), "r"(b[0]), "r"(b[1]));
}
__device__ __forceinline__ uint32_t pack2(float a, float b, uint32_t& lo) {
    __nv_bfloat16 ha = __float2bfloat16(a), hb = __float2bfloat16(b);
    __nv_bfloat16 la = __float2bfloat16(a - __bfloat162float(ha));
    __nv_bfloat16 lb = __float2bfloat16(b - __bfloat162float(hb));
    lo = (uint32_t)__bfloat16_as_ushort(la) | ((uint32_t)__bfloat16_as_ushort(lb) << 16);
    return (uint32_t)__bfloat16_as_ushort(ha) | ((uint32_t)__bfloat16_as_ushort(hb) << 16);
}

// ---------------- staging via cp.async ----------------
__device__ __forceinline__ void stageR(uint32_t dh, uint32_t dl,
    const __nv_bfloat16* __restrict__ gh, const __nv_bfloat16* __restrict__ gl,
    size_t stride)
{
    const int r = threadIdx.x >> 1, p = threadIdx.x & 1;
    const char* s0 = (const char*)(gh + (size_t)r * stride) + p * 32;
    const char* s1 = (const char*)(gl + (size_t)r * stride) + p * 32;
    const uint32_t o = r * 80 + p * 32;
    cpa16(dh + o, s0); cpa16(dh + o + 16, s0 + 16);
    cpa16(dl + o, s1); cpa16(dl + o + 16, s1 + 16);
}
__device__ __forceinline__ void stageB(uint32_t dh, uint32_t dl,
    const __nv_bfloat16* __restrict__ gh, const __nv_bfloat16* __restrict__ gl,
    size_t stride)
{
    const int k = threadIdx.x >> 3, seg = threadIdx.x & 7;
    const char* s0 = (const char*)(gh + (size_t)k * stride) + seg * 32;
    const char* s1 = (const char*)(gl + (size_t)k * stride) + seg * 32;
    const uint32_t o = k * 272 + seg * 32;
    cpa16(dh + o, s0); cpa16(dh + o + 16, s0 + 16);
    cpa16(dl + o, s1); cpa16(dl + o + 16, s1 + 16);
}

// ---------------- mma compute for one 32-K chunk (A-frag reuse) -------------
template<bool BT>
__device__ __forceinline__ void compute32(const char* smb, float acc[4][4][4])
{
    const int t = threadIdx.x, lane = t & 31, w = t >> 5;
    const int wm = w & 1, wn = w >> 1;
    const int ar = wm * 64 + (lane & 15);
    const int ac = (lane >> 4) * 8;
    const int btr = lane & 15;
    const int btc = wn * 32;
    const int nr = wn * 32 + (lane & 7);
    const int nc = ((lane >> 3) & 1) * 8;

    const __nv_bfloat16* Ah = (const __nv_bfloat16*)(smb + (BT ? NN_AH : NT_AH));
    const __nv_bfloat16* Al = (const __nv_bfloat16*)(smb + (BT ? NN_AL : NT_AL));
    const __nv_bfloat16* Bh = (const __nv_bfloat16*)(smb + (BT ? NN_BH : NT_BH));
    const __nv_bfloat16* Bl = (const __nv_bfloat16*)(smb + (BT ? NN_BL : NT_BL));

    #pragma unroll
    for (int kk = 0; kk < 2; kk++) {
        uint32_t ah[4][4], al[4][4], bq[4][2];
        #pragma unroll
        for (int mi = 0; mi < 4; mi++) {
            ldm4(ah[mi], Ah + (ar + mi * 16) * 40 + kk * 16 + ac);
            ldm4(al[mi], Al + (ar + mi * 16) * 40 + kk * 16 + ac);
        }
        #pragma unroll
        for (int ni = 0; ni < 4; ni++) {
            if (BT) ldm2t(bq[ni], Bh + (kk * 16 + btr) * 136 + btc + ni * 8);
            else    ldm2 (bq[ni], Bh + (nr + ni * 8) * 40 + kk * 16 + nc);
        }
        #pragma unroll
        for (int mi = 0; mi < 4; mi++)
            #pragma unroll
            for (int ni = 0; ni < 4; ni++)
                mma_bf(acc[mi][ni], ah[mi], bq[ni]);
        #pragma unroll
        for (int mi = 0; mi < 4; mi++)
            #pragma unroll
            for (int ni = 0; ni < 4; ni++)
                mma_bf(acc[mi][ni], al[mi], bq[ni]);
        #pragma unroll
        for (int ni = 0; ni < 4; ni++) {
            if (BT) ldm2t(bq[ni], Bl + (kk * 16 + btr) * 136 + btc + ni * 8);
            else    ldm2 (bq[ni], Bl + (nr + ni * 8) * 40 + kk * 16 + nc);
        }
        #pragma unroll
        for (int mi = 0; mi < 4; mi++)
            #pragma unroll
            for (int ni = 0; ni < 4; ni++)
                mma_bf(acc[mi][ni], ah[mi], bq[ni]);
    }
}

#define ACC_ZERO(acc) { \
    _Pragma("unroll") for (int _a = 0; _a < 4; _a++) \
    _Pragma("unroll") for (int _c = 0; _c < 4; _c++) \
    _Pragma("unroll") for (int _d = 0; _d < 4; _d++) acc[_a][_c][_d] = 0.f; }

// 3-stage, 1-sync mainloop for NN kernels (8 chunks of K=32)
#define NN_MAINLOOP(Agh, Agl, Bgh, Bgl) { \
    stageR(sb + NN_AH, sb + NN_AL, Agh, Agl, CC); \
    stageB(sb + NN_BH, sb + NN_BL, Bgh, Bgl, NSP); \
    CP_COMMIT(); \
    stageR(sb + NN_STG + NN_AH, sb + NN_STG + NN_AL, Agh + 32, Agl + 32, CC); \
    stageB(sb + NN_STG + NN_BH, sb + NN_STG + NN_BL, \
           Bgh + (size_t)32 * NSP, Bgl + (size_t)32 * NSP, NSP); \
    CP_COMMIT(); \
    _Pragma("unroll 1") \
    for (int ch = 0; ch < 8; ch++) { \
        if (ch < 7) { CP_WAIT(1); } else { CP_WAIT(0); } \
        __syncthreads(); \
        if (ch + 2 < 8) { \
            const int kn = (ch + 2) * 32; \
            const uint32_t bb = sb + ((ch + 2) % 3) * NN_STG; \
            stageR(bb + NN_AH, bb + NN_AL, Agh + kn, Agl + kn, CC); \
            stageB(bb + NN_BH, bb + NN_BL, \
                   Bgh + (size_t)kn * NSP, Bgl + (size_t)kn * NSP, NSP); \
            CP_COMMIT(); \
        } \
        compute32<true>(sm + (ch % 3) * NN_STG, acc); \
    } }

// ---------------- K1: E = exp(Wk @ x) + rowsums ----------------
__global__ void __launch_bounds__(256, 2)
k_exp()
{
    extern __shared__ char sm[];
    const uint32_t sb = smem_u32(sm);
    const int b = blockIdx.z, m0 = blockIdx.y * 128, n0 = blockIdx.x * 128;

    const __nv_bfloat16* Agh = g_Wkh + (size_t)m0 * CC;
    const __nv_bfloat16* Agl = g_Wkl + (size_t)m0 * CC;
    const __nv_bfloat16* Bgh = g_xh + (size_t)b * CC * NSP + n0;
    const __nv_bfloat16* Bgl = g_xl + (size_t)b * CC * NSP + n0;

    float acc[4][4][4]; ACC_ZERO(acc);
    NN_MAINLOOP(Agh, Agl, Bgh, Bgl);

    const int t = threadIdx.x, lane = t & 31, w = t >> 5;
    const int wm = w & 1, wn = w >> 1;
    const int rbase = m0 + wm * 64 + (lane >> 2);
    const int cbase = n0 + wn * 32 + (lane & 3) * 2;
    __nv_bfloat16* Eh = g_Eh + (size_t)b * CC * NSP;
    __nv_bfloat16* El = g_El + (size_t)b * CC * NSP;

    float rs[8] = {0, 0, 0, 0, 0, 0, 0, 0};
    #pragma unroll
    for (int mi = 0; mi < 4; mi++)
        #pragma unroll
        for (int h = 0; h < 2; h++) {
            const int rr = rbase + mi * 16 + 8 * h;
            #pragma unroll
            for (int ni = 0; ni < 4; ni++) {
                float e0 = __expf(acc[mi][ni][2 * h + 0]);
                float e1 = __expf(acc[mi][ni][2 * h + 1]);
                rs[mi * 2 + h] += e0 + e1;
                uint32_t lp, hp = pack2(e0, e1, lp);
                const size_t off = (size_t)rr * NSP + cbase + ni * 8;
                *(uint32_t*)(Eh + off) = hp;
                *(uint32_t*)(El + off) = lp;
            }
        }
    #pragma unroll
    for (int i = 0; i < 8; i++) {
        float v = rs[i];
        v += __shfl_xor_sync(0xffffffffu, v, 1);
        v += __shfl_xor_sync(0xffffffffu, v, 2);
        if ((lane & 3) == 0) {
            const int rr = rbase + (i >> 1) * 16 + 8 * (i & 1);
            atomicAdd(&g_rowsum[b * CC + rr], v);
        }
    }
}

// ---------------- K5: out = relu(M @ x + bias) ----------------
__global__ void __launch_bounds__(256, 2)
k_out(const float* __restrict__ gamma, const float* __restrict__ beta,
      const float* __restrict__ mean,  const float* __restrict__ var,
      float* __restrict__ out)
{
    extern __shared__ char sm[];
    const uint32_t sb = smem_u32(sm);
    const int b = blockIdx.z, m0 = blockIdx.y * 128, n0 = blockIdx.x * 128;

    const __nv_bfloat16* Agh = g_Mh + (size_t)b * CC * CC + (size_t)m0 * CC;
    const __nv_bfloat16* Agl = g_Ml + (size_t)b * CC * CC + (size_t)m0 * CC;
    const __nv_bfloat16* Bgh = g_xh + (size_t)b * CC * NSP + n0;
    const __nv_bfloat16* Bgl = g_xl + (size_t)b * CC * NSP + n0;

    float acc[4][4][4]; ACC_ZERO(acc);
    NN_MAINLOOP(Agh, Agl, Bgh, Bgl);

    const int t = threadIdx.x, lane = t & 31, w = t >> 5;
    const int wm = w & 1, wn = w >> 1;
    const int rbase = m0 + wm * 64 + (lane >> 2);
    const int cbase = n0 + wn * 32 + (lane & 3) * 2;
    float* Ob = out + (size_t)b * CC * NSP;

    #pragma unroll
    for (int mi = 0; mi < 4; mi++)
        #pragma unroll
        for (int h = 0; h < 2; h++) {
            const int o = rbase + mi * 16 + 8 * h;
            const float inv  = gamma[o] * rsqrtf(var[o] + EPS);
            const float bias = beta[o] - mean[o] * inv;
            #pragma unroll
            for (int ni = 0; ni < 4; ni++) {
                float2 v;
                v.x = fmaxf(acc[mi][ni][2 * h + 0] + bias, 0.f);
                v.y = fmaxf(acc[mi][ni][2 * h + 1] + bias, 0.f);
                *(float2*)(Ob + (size_t)o * NSP + cbase + ni * 8) = v;
            }
        }
}

// ---------- K2: St partial slabs (atomic-free, 2-stage, ONE sync/chunk) -----
__global__ void __launch_bounds__(256, 2)
k_st()
{
    extern __shared__ char sm[];
    const uint32_t sb = smem_u32(sm);
    const int c0 = blockIdx.x * 128, e0 = blockIdx.y * 128;
    const int b = blockIdx.z >> 3, ks = blockIdx.z & 7;
    const int kbeg = ks * (NSP / KSPLIT);     // 2048 per split
    const int NCH = (NSP / KSPLIT) / 32;      // 64 chunks

    const __nv_bfloat16* Agh = g_xh + (size_t)(b * CC + e0) * NSP + kbeg;
    const __nv_bfloat16* Agl = g_xl + (size_t)(b * CC + e0) * NSP + kbeg;
    const __nv_bfloat16* Bgh = g_Eh + (size_t)(b * CC + c0) * NSP + kbeg;
    const __nv_bfloat16* Bgl = g_El + (size_t)(b * CC + c0) * NSP + kbeg;

    float acc[4][4][4]; ACC_ZERO(acc);

    stageR(sb + NT_AH, sb + NT_AL, Agh, Agl, NSP);
    stageR(sb + NT_BH, sb + NT_BL, Bgh, Bgl, NSP);
    CP_COMMIT();
    #pragma unroll 1
    for (int ch = 0; ch < NCH; ch++) {
        CP_WAIT(0);            // stage(ch) complete
        __syncthreads();       // all warps see it; all done with compute(ch-1)
        if (ch + 1 < NCH) {
            const int kn = (ch + 1) * 32;
            const uint32_t bb = sb + ((ch + 1) & 1) * NT_STG;
            stageR(bb + NT_AH, bb + NT_AL, Agh + kn, Agl + kn, NSP);
            stageR(bb + NT_BH, bb + NT_BL, Bgh + kn, Bgl + kn, NSP);
            CP_COMMIT();
        }
        compute32<false>(sm + (ch & 1) * NT_STG, acc);
    }

    const int t = threadIdx.x, lane = t & 31, w = t >> 5;
    const int wm = w & 1, wn = w >> 1;
    const int rbase = e0 + wm * 64 + (lane >> 2);
    const int cbase = c0 + wn * 32 + (lane & 3) * 2;
    float* Sp = g_Stp + ((size_t)ks * BB + b) * CC * CC;

    #pragma unroll
    for (int mi = 0; mi < 4; mi++)
        #pragma unroll
        for (int h = 0; h < 2; h++) {
            const int rr = rbase + mi * 16 + 8 * h;
            #pragma unroll
            for (int ni = 0; ni < 4; ni++) {
                float2 v;
                v.x = acc[mi][ni][2 * h + 0];
                v.y = acc[mi][ni][2 * h + 1];
                *(float2*)(Sp + (size_t)rr * CC + cbase + ni * 8) = v;
            }
        }
}

// ---------------- reduce slabs (float4) ----------------
__global__ void k_sum()
{
    const size_t i = ((size_t)blockIdx.x * 256 + threadIdx.x) * 4;
    const size_t STRIDE = (size_t)BB * CC * CC;
    float4 s = make_float4(0.f, 0.f, 0.f, 0.f);
    #pragma unroll
    for (int ks = 0; ks < KSPLIT; ks++) {
        float4 v = *(const float4*)(g_Stp + ks * STRIDE + i);
        s.x += v.x; s.y += v.y; s.z += v.z; s.w += v.w;
    }
    *(float4*)(g_St + i) = s;
}

// ---------------- prep: split x and Wk to bf16 hi/lo ----------------
__global__ void k_prep_x(const float* __restrict__ x)
{
    const size_t i = (size_t)blockIdx.x * 256 + threadIdx.x;
    float4 f = ((const float4*)x)[i];
    uint32_t l0, l1;
    uint32_t h0 = pack2(f.x, f.y, l0);
    uint32_t h1 = pack2(f.z, f.w, l1);
    *(uint2*)(g_xh + 4 * i) = make_uint2(h0, h1);
    *(uint2*)(g_xl + 4 * i) = make_uint2(l0, l1);
}
__global__ void k_prep_w(const float* __restrict__ w_qkv)
{
    int i = blockIdx.x * 256 + threadIdx.x;
    float v = w_qkv[CC * CC + i];
    __nv_bfloat16 h = __float2bfloat16(v);
    g_Wkh[i] = h;
    g_Wkl[i] = __float2bfloat16(v - __bfloat162float(h));
}

// ---------------- fp32 64x64 core for small middle GEMMs ----------------
// BSCALE: B row k scaled by 1/bscale[k] (reciprocal computed inline)
template<bool BSCALE>
__device__ __forceinline__ void core64(
    const float* __restrict__ A, int lda,
    const float* __restrict__ B, int ldb,
    const float* __restrict__ bscale, float acc[4][4])
{
    __shared__ __align__(16) float As[16][68];
    __shared__ __align__(16) float Bs[16][68];
    const int t = threadIdx.x, tx = t & 15, ty = t >> 4;

    for (int k0 = 0; k0 < CC; k0 += 16) {
        __syncthreads();
        {
            const int r = t >> 2, q = t & 3;
            float4 a4 = *(const float4*)(A + (size_t)r * lda + k0 + 4 * q);
            As[4*q+0][r] = a4.x; As[4*q+1][r] = a4.y; As[4*q+2][r] = a4.z; As[4*q+3][r] = a4.w;
            const int kr = t >> 4, c0 = (t & 15) * 4;
            float4 b4 = *(const float4*)(B + (size_t)(k0 + kr) * ldb + c0);
            if (BSCALE) {
                float s = 1.0f / bscale[k0 + kr];
                b4.x *= s; b4.y *= s; b4.z *= s; b4.w *= s;
            }
            *(float4*)&Bs[kr][c0] = b4;
        }
        __syncthreads();
        #pragma unroll
        for (int k = 0; k < 16; k++) {
            float4 a4 = *(const float4*)&As[k][ty * 4];
            float4 b4 = *(const float4*)&Bs[k][tx * 4];
            float av[4] = {a4.x, a4.y, a4.z, a4.w};
            float bv[4] = {b4.x, b4.y, b4.z, b4.w};
            #pragma unroll
            for (int i = 0; i < 4; i++)
                #pragma unroll
                for (int j = 0; j < 4; j++)
                    acc[i][j] += av[i] * bv[j];
        }
    }
}

__global__ void __launch_bounds__(256)
k_w2(const float* __restrict__ w_proj, const float* __restrict__ w_qkv)
{
    const int m0 = blockIdx.y * 64, n0 = blockIdx.x * 64;
    float acc[4][4] = {};
    core64<false>(w_proj + (size_t)m0 * CC, CC,
                  w_qkv + (size_t)2 * CC * CC + n0, CC, nullptr, acc);
    const int tx = threadIdx.x & 15, ty = threadIdx.x >> 4;
    #pragma unroll
    for (int i = 0; i < 4; i++)
        #pragma unroll
        for (int j = 0; j < 4; j++)
            g_W2[(m0 + ty * 4 + i) * CC + n0 + tx * 4 + j] = acc[i][j];
}

__global__ void __launch_bounds__(256)
k_r(const float* __restrict__ w_qkv)
{
    const int b = blockIdx.z, m0 = blockIdx.y * 64, n0 = blockIdx.x * 64;
    float acc[4][4] = {};
    core64<true>(g_St + (size_t)b * CC * CC + (size_t)m0 * CC, CC,
                 w_qkv + n0, CC, g_rowsum + b * CC, acc);
    const int tx = threadIdx.x & 15, ty = threadIdx.x >> 4;
    float* Rb = g_R + (size_t)b * CC * CC;
    #pragma unroll
    for (int i = 0; i < 4; i++)
        #pragma unroll
        for (int j = 0; j < 4; j++)
            Rb[(m0 + ty * 4 + i) * CC + n0 + tx * 4 + j] = acc[i][j];
}

__global__ void __launch_bounds__(256)
k_m(const float* __restrict__ gamma, const float* __restrict__ var)
{
    const int b = blockIdx.z, m0 = blockIdx.y * 64, n0 = blockIdx.x * 64;
    float acc[4][4] = {};
    core64<false>(g_W2 + (size_t)m0 * CC, CC,
                  g_R + (size_t)b * CC * CC + n0, CC, nullptr, acc);
    const int tx = threadIdx.x & 15, ty = threadIdx.x >> 4;
    __nv_bfloat16* Mh = g_Mh + (size_t)b * CC * CC;
    __nv_bfloat16* Ml = g_Ml + (size_t)b * CC * CC;
    #pragma unroll
    for (int i = 0; i < 4; i++) {
        const int o = m0 + ty * 4 + i;
        const float inv = gamma[o] * rsqrtf(var[o] + EPS);
        #pragma unroll
        for (int j = 0; j < 4; j++) {
            float v = inv * acc[i][j];
            __nv_bfloat16 h = __float2bfloat16(v);
            Mh[o * CC + n0 + tx * 4 + j] = h;
            Ml[o * CC + n0 + tx * 4 + j] = __float2bfloat16(v - __bfloat162float(h));
        }
    }
}

// ---------------- launch ----------------
extern "C" void kernel_launch(void* const* d_in, const int* in_sizes, int n_in,
                              void* d_out, int out_size)
{
    const float* x      = (const float*)d_in[0];
    const float* w_qkv  = (const float*)d_in[1];
    const float* w_proj = (const float*)d_in[2];
    const float* gamma  = (const float*)d_in[3];
    const float* beta   = (const float*)d_in[4];
    const float* mean   = (const float*)d_in[5];
    const float* var    = (const float*)d_in[6];
    float* out = (float*)d_out;

    cudaFuncSetAttribute(k_exp, cudaFuncAttributeMaxDynamicSharedMemorySize, NN_SMEM);
    cudaFuncSetAttribute(k_out, cudaFuncAttributeMaxDynamicSharedMemorySize, NN_SMEM);
    cudaFuncSetAttribute(k_st,  cudaFuncAttributeMaxDynamicSharedMemorySize, NT_SMEM);

    void* p_rowsum = nullptr;
    cudaGetSymbolAddress(&p_rowsum, g_rowsum);
    cudaMemsetAsync(p_rowsum, 0, (size_t)BB * CC * sizeof(float));

    dim3 blk(256);
    k_prep_x<<<dim3((size_t)BB * CC * NSP / 1024), blk>>>(x);
    k_prep_w<<<dim3(CC * CC / 256), blk>>>(w_qkv);
    k_w2<<<dim3(4, 4), blk>>>(w_proj, w_qkv);
    k_exp<<<dim3(NSP / 128, 2, BB), blk, NN_SMEM>>>();
    k_st<<<dim3(2, 2, BB * KSPLIT), blk, NT_SMEM>>>();
    k_sum<<<dim3(BB * CC * CC / 1024), blk>>>();
    k_r<<<dim3(4, 4, BB), blk>>>(w_qkv);
    k_m<<<dim3(4, 4, BB), blk>>>(gamma, var);
    k_out<<<dim3(NSP / 128, 2, BB), blk, NN_SMEM>>>(gamma, beta, mean, var, out);
}

// round 14
// speedup vs baseline: 1.0852x; 1.0039x over previous
#include <cuda_runtime.h>
#include <cuda_bf16.h>
#include <math.h>
#include <stdint.h>

#define CC   256
#define NSP  16384
#define BB   8
#define EPS  1e-5f
#define KSPLIT 8

// ---------------- scratch (device globals) ----------------
__device__ __nv_bfloat16 g_xh[(size_t)BB * CC * NSP], g_xl[(size_t)BB * CC * NSP];
__device__ __nv_bfloat16 g_Eh[(size_t)BB * CC * NSP], g_El[(size_t)BB * CC * NSP];
__device__ float g_rowsum[BB * CC];
__device__ float g_Stp[(size_t)KSPLIT * BB * CC * CC];
__device__ float g_St[BB * CC * CC];
__device__ float g_R[BB * CC * CC];
__device__ float g_W2[CC * CC];
__device__ __nv_bfloat16 g_Wkh[CC * CC], g_Wkl[CC * CC];
__device__ __nv_bfloat16 g_Mh[BB * CC * CC], g_Ml[BB * CC * CC];

// ---------------- smem stage layouts ----------------
// NN kernels (k_exp/k_out): A [128][40] hi/lo + B(x^T) [32][136] hi/lo, 3-stage
#define NN_AH 0
#define NN_AL 10240
#define NN_BH 20480
#define NN_BL 29184
#define NN_STG 37888
#define NN_SMEM (3 * NN_STG)    // 113664 -> 2 CTAs/SM
// NT kernel (k_st): A,B both [128][40] hi/lo, 2-stage
#define NT_AH 0
#define NT_AL 10240
#define NT_BH 20480
#define NT_BL 30720
#define NT_STG 40960
#define NT_SMEM (2 * NT_STG)    // 81920 -> 2 CTAs/SM

// ---------------- helpers ----------------
__device__ __forceinline__ uint32_t smem_u32(const void* p) {
    uint32_t a;
    asm("{ .reg .u64 t; cvta.to.shared.u64 t, %1; cvt.u32.u64 %0, t; }" : "=r"(a) : "l"(p));
    return a;
}
__device__ __forceinline__ void cpa16(uint32_t dst, const void* src) {
    asm volatile("cp.async.cg.shared.global [%0], [%1], 16;" :: "r"(dst), "l"(src));
}
#define CP_COMMIT()  asm volatile("cp.async.commit_group;")
#define CP_WAIT(n)   asm volatile("cp.async.wait_group %0;" :: "n"(n))

__device__ __forceinline__ void ldm4(uint32_t* r, const void* p) {
    uint32_t a = (uint32_t)__cvta_generic_to_shared(p);
    asm volatile("ldmatrix.sync.aligned.m8n8.x4.shared.b16 {%0,%1,%2,%3},[%4];"
                 : "=r"(r[0]), "=r"(r[1]), "=r"(r[2]), "=r"(r[3]) : "r"(a));
}
__device__ __forceinline__ void ldm2(uint32_t* r, const void* p) {
    uint32_t a = (uint32_t)__cvta_generic_to_shared(p);
    asm volatile("ldmatrix.sync.aligned.m8n8.x2.shared.b16 {%0,%1},[%2];"
                 : "=r"(r[0]), "=r"(r[1]) : "r"(a));
}
__device__ __forceinline__ void ldm2t(uint32_t* r, const void* p) {
    uint32_t a = (uint32_t)__cvta_generic_to_shared(p);
    asm volatile("ldmatrix.sync.aligned.m8n8.x2.trans.shared.b16 {%0,%1},[%2];"
                 : "=r"(r[0]), "=r"(r[1]) : "r"(a));
}
__device__ __forceinline__ void mma_bf(float* d, const uint32_t* a, const uint32_t* b) {
    asm volatile("mma.sync.aligned.m16n8k16.row.col.f32.bf16.bf16.f32 "
                 "{%0,%1,%2,%3},{%4,%5,%6,%7},{%8,%9},{%0,%1,%2,%3};"
                 : "+f"(d[0]), "+f"(d[1]), "+f"(d[2]), "+f"(d[3])
                 : "r"(a[0]), "r"(a[1]), "r"(a[2]), "r"(a[3]), "r"(b[0]), "r"(b[1]));
}
__device__ __forceinline__ uint32_t pack2(float a, float b, uint32_t& lo) {
    __nv_bfloat16 ha = __float2bfloat16(a), hb = __float2bfloat16(b);
    __nv_bfloat16 la = __float2bfloat16(a - __bfloat162float(ha));
    __nv_bfloat16 lb = __float2bfloat16(b - __bfloat162float(hb));
    lo = (uint32_t)__bfloat16_as_ushort(la) | ((uint32_t)__bfloat16_as_ushort(lb) << 16);
    return (uint32_t)__bfloat16_as_ushort(ha) | ((uint32_t)__bfloat16_as_ushort(hb) << 16);
}

// ---------------- staging via cp.async ----------------
__device__ __forceinline__ void stageR(uint32_t dh, uint32_t dl,
    const __nv_bfloat16* __restrict__ gh, const __nv_bfloat16* __restrict__ gl,
    size_t stride)
{
    const int r = threadIdx.x >> 1, p = threadIdx.x & 1;
    const char* s0 = (const char*)(gh + (size_t)r * stride) + p * 32;
    const char* s1 = (const char*)(gl + (size_t)r * stride) + p * 32;
    const uint32_t o = r * 80 + p * 32;
    cpa16(dh + o, s0); cpa16(dh + o + 16, s0 + 16);
    cpa16(dl + o, s1); cpa16(dl + o + 16, s1 + 16);
}
__device__ __forceinline__ void stageB(uint32_t dh, uint32_t dl,
    const __nv_bfloat16* __restrict__ gh, const __nv_bfloat16* __restrict__ gl,
    size_t stride)
{
    const int k = threadIdx.x >> 3, seg = threadIdx.x & 7;
    const char* s0 = (const char*)(gh + (size_t)k * stride) + seg * 32;
    const char* s1 = (const char*)(gl + (size_t)k * stride) + seg * 32;
    const uint32_t o = k * 272 + seg * 32;
    cpa16(dh + o, s0); cpa16(dh + o + 16, s0 + 16);
    cpa16(dl + o, s1); cpa16(dl + o + 16, s1 + 16);
}

// ---------------- mma compute for one 32-K chunk (A-frag reuse) -------------
template<bool BT>
__device__ __forceinline__ void compute32(const char* smb, float acc[4][4][4])
{
    const int t = threadIdx.x, lane = t & 31, w = t >> 5;
    const int wm = w & 1, wn = w >> 1;
    const int ar = wm * 64 + (lane & 15);
    const int ac = (lane >> 4) * 8;
    const int btr = lane & 15;
    const int btc = wn * 32;
    const int nr = wn * 32 + (lane & 7);
    const int nc = ((lane >> 3) & 1) * 8;

    const __nv_bfloat16* Ah = (const __nv_bfloat16*)(smb + (BT ? NN_AH : NT_AH));
    const __nv_bfloat16* Al = (const __nv_bfloat16*)(smb + (BT ? NN_AL : NT_AL));
    const __nv_bfloat16* Bh = (const __nv_bfloat16*)(smb + (BT ? NN_BH : NT_BH));
    const __nv_bfloat16* Bl = (const __nv_bfloat16*)(smb + (BT ? NN_BL : NT_BL));

    #pragma unroll
    for (int kk = 0; kk < 2; kk++) {
        uint32_t ah[4][4], al[4][4], bq[4][2];
        #pragma unroll
        for (int mi = 0; mi < 4; mi++) {
            ldm4(ah[mi], Ah + (ar + mi * 16) * 40 + kk * 16 + ac);
            ldm4(al[mi], Al + (ar + mi * 16) * 40 + kk * 16 + ac);
        }
        #pragma unroll
        for (int ni = 0; ni < 4; ni++) {
            if (BT) ldm2t(bq[ni], Bh + (kk * 16 + btr) * 136 + btc + ni * 8);
            else    ldm2 (bq[ni], Bh + (nr + ni * 8) * 40 + kk * 16 + nc);
        }
        #pragma unroll
        for (int mi = 0; mi < 4; mi++)
            #pragma unroll
            for (int ni = 0; ni < 4; ni++)
                mma_bf(acc[mi][ni], ah[mi], bq[ni]);
        #pragma unroll
        for (int mi = 0; mi < 4; mi++)
            #pragma unroll
            for (int ni = 0; ni < 4; ni++)
                mma_bf(acc[mi][ni], al[mi], bq[ni]);
        #pragma unroll
        for (int ni = 0; ni < 4; ni++) {
            if (BT) ldm2t(bq[ni], Bl + (kk * 16 + btr) * 136 + btc + ni * 8);
            else    ldm2 (bq[ni], Bl + (nr + ni * 8) * 40 + kk * 16 + nc);
        }
        #pragma unroll
        for (int mi = 0; mi < 4; mi++)
            #pragma unroll
            for (int ni = 0; ni < 4; ni++)
                mma_bf(acc[mi][ni], ah[mi], bq[ni]);
    }
}

#define ACC_ZERO(acc) { \
    _Pragma("unroll") for (int _a = 0; _a < 4; _a++) \
    _Pragma("unroll") for (int _c = 0; _c < 4; _c++) \
    _Pragma("unroll") for (int _d = 0; _d < 4; _d++) acc[_a][_c][_d] = 0.f; }

// 3-stage, 1-sync mainloop for NN kernels (8 chunks of K=32)
#define NN_MAINLOOP(Agh, Agl, Bgh, Bgl) { \
    stageR(sb + NN_AH, sb + NN_AL, Agh, Agl, CC); \
    stageB(sb + NN_BH, sb + NN_BL, Bgh, Bgl, NSP); \
    CP_COMMIT(); \
    stageR(sb + NN_STG + NN_AH, sb + NN_STG + NN_AL, Agh + 32, Agl + 32, CC); \
    stageB(sb + NN_STG + NN_BH, sb + NN_STG + NN_BL, \
           Bgh + (size_t)32 * NSP, Bgl + (size_t)32 * NSP, NSP); \
    CP_COMMIT(); \
    _Pragma("unroll 1") \
    for (int ch = 0; ch < 8; ch++) { \
        if (ch < 7) { CP_WAIT(1); } else { CP_WAIT(0); } \
        __syncthreads(); \
        if (ch + 2 < 8) { \
            const int kn = (ch + 2) * 32; \
            const uint32_t bb = sb + ((ch + 2) % 3) * NN_STG; \
            stageR(bb + NN_AH, bb + NN_AL, Agh + kn, Agl + kn, CC); \
            stageB(bb + NN_BH, bb + NN_BL, \
                   Bgh + (size_t)kn * NSP, Bgl + (size_t)kn * NSP, NSP); \
            CP_COMMIT(); \
        } \
        compute32<true>(sm + (ch % 3) * NN_STG, acc); \
    } }

// ---------------- K1: E = exp(Wk @ x) + rowsums ----------------
__global__ void __launch_bounds__(256, 2)
k_exp()
{
    extern __shared__ char sm[];
    const uint32_t sb = smem_u32(sm);
    const int b = blockIdx.z, m0 = blockIdx.y * 128, n0 = blockIdx.x * 128;

    const __nv_bfloat16* Agh = g_Wkh + (size_t)m0 * CC;
    const __nv_bfloat16* Agl = g_Wkl + (size_t)m0 * CC;
    const __nv_bfloat16* Bgh = g_xh + (size_t)b * CC * NSP + n0;
    const __nv_bfloat16* Bgl = g_xl + (size_t)b * CC * NSP + n0;

    float acc[4][4][4]; ACC_ZERO(acc);
    NN_MAINLOOP(Agh, Agl, Bgh, Bgl);

    const int t = threadIdx.x, lane = t & 31, w = t >> 5;
    const int wm = w & 1, wn = w >> 1;
    const int rbase = m0 + wm * 64 + (lane >> 2);
    const int cbase = n0 + wn * 32 + (lane & 3) * 2;
    __nv_bfloat16* Eh = g_Eh + (size_t)b * CC * NSP;
    __nv_bfloat16* El = g_El + (size_t)b * CC * NSP;

    float rs[8] = {0, 0, 0, 0, 0, 0, 0, 0};
    #pragma unroll
    for (int mi = 0; mi < 4; mi++)
        #pragma unroll
        for (int h = 0; h < 2; h++) {
            const int rr = rbase + mi * 16 + 8 * h;
            #pragma unroll
            for (int ni = 0; ni < 4; ni++) {
                float e0 = __expf(acc[mi][ni][2 * h + 0]);
                float e1 = __expf(acc[mi][ni][2 * h + 1]);
                rs[mi * 2 + h] += e0 + e1;
                uint32_t lp, hp = pack2(e0, e1, lp);
                const size_t off = (size_t)rr * NSP + cbase + ni * 8;
                *(uint32_t*)(Eh + off) = hp;
                *(uint32_t*)(El + off) = lp;
            }
        }
    #pragma unroll
    for (int i = 0; i < 8; i++) {
        float v = rs[i];
        v += __shfl_xor_sync(0xffffffffu, v, 1);
        v += __shfl_xor_sync(0xffffffffu, v, 2);
        if ((lane & 3) == 0) {
            const int rr = rbase + (i >> 1) * 16 + 8 * (i & 1);
            atomicAdd(&g_rowsum[b * CC + rr], v);
        }
    }
}

// ---------------- K5: out = relu(M @ x + bias) ----------------
__global__ void __launch_bounds__(256, 2)
k_out(const float* __restrict__ gamma, const float* __restrict__ beta,
      const float* __restrict__ mean,  const float* __restrict__ var,
      float* __restrict__ out)
{
    extern __shared__ char sm[];
    const uint32_t sb = smem_u32(sm);
    const int b = blockIdx.z, m0 = blockIdx.y * 128, n0 = blockIdx.x * 128;

    const __nv_bfloat16* Agh = g_Mh + (size_t)b * CC * CC + (size_t)m0 * CC;
    const __nv_bfloat16* Agl = g_Ml + (size_t)b * CC * CC + (size_t)m0 * CC;
    const __nv_bfloat16* Bgh = g_xh + (size_t)b * CC * NSP + n0;
    const __nv_bfloat16* Bgl = g_xl + (size_t)b * CC * NSP + n0;

    float acc[4][4][4]; ACC_ZERO(acc);
    NN_MAINLOOP(Agh, Agl, Bgh, Bgl);

    const int t = threadIdx.x, lane = t & 31, w = t >> 5;
    const int wm = w & 1, wn = w >> 1;
    const int rbase = m0 + wm * 64 + (lane >> 2);
    const int cbase = n0 + wn * 32 + (lane & 3) * 2;
    float* Ob = out + (size_t)b * CC * NSP;

    #pragma unroll
    for (int mi = 0; mi < 4; mi++)
        #pragma unroll
        for (int h = 0; h < 2; h++) {
            const int o = rbase + mi * 16 + 8 * h;
            const float inv  = gamma[o] * rsqrtf(var[o] + EPS);
            const float bias = beta[o] - mean[o] * inv;
            #pragma unroll
            for (int ni = 0; ni < 4; ni++) {
                float2 v;
                v.x = fmaxf(acc[mi][ni][2 * h + 0] + bias, 0.f);
                v.y = fmaxf(acc[mi][ni][2 * h + 1] + bias, 0.f);
                *(float2*)(Ob + (size_t)o * NSP + cbase + ni * 8) = v;
            }
        }
}

// ---------- K2: St partial slabs (atomic-free, 2-stage, ONE sync/chunk) -----
__global__ void __launch_bounds__(256, 2)
k_st()
{
    extern __shared__ char sm[];
    const uint32_t sb = smem_u32(sm);
    const int c0 = blockIdx.x * 128, e0 = blockIdx.y * 128;
    const int b = blockIdx.z >> 3, ks = blockIdx.z & 7;
    const int kbeg = ks * (NSP / KSPLIT);     // 2048 per split
    const int NCH = (NSP / KSPLIT) / 32;      // 64 chunks

    const __nv_bfloat16* Agh = g_xh + (size_t)(b * CC + e0) * NSP + kbeg;
    const __nv_bfloat16* Agl = g_xl + (size_t)(b * CC + e0) * NSP + kbeg;
    const __nv_bfloat16* Bgh = g_Eh + (size_t)(b * CC + c0) * NSP + kbeg;
    const __nv_bfloat16* Bgl = g_El + (size_t)(b * CC + c0) * NSP + kbeg;

    float acc[4][4][4]; ACC_ZERO(acc);

    stageR(sb + NT_AH, sb + NT_AL, Agh, Agl, NSP);
    stageR(sb + NT_BH, sb + NT_BL, Bgh, Bgl, NSP);
    CP_COMMIT();
    #pragma unroll 1
    for (int ch = 0; ch < NCH; ch++) {
        CP_WAIT(0);
        __syncthreads();
        if (ch + 1 < NCH) {
            const int kn = (ch + 1) * 32;
            const uint32_t bb = sb + ((ch + 1) & 1) * NT_STG;
            stageR(bb + NT_AH, bb + NT_AL, Agh + kn, Agl + kn, NSP);
            stageR(bb + NT_BH, bb + NT_BL, Bgh + kn, Bgl + kn, NSP);
            CP_COMMIT();
        }
        compute32<false>(sm + (ch & 1) * NT_STG, acc);
    }

    const int t = threadIdx.x, lane = t & 31, w = t >> 5;
    const int wm = w & 1, wn = w >> 1;
    const int rbase = e0 + wm * 64 + (lane >> 2);
    const int cbase = c0 + wn * 32 + (lane & 3) * 2;
    float* Sp = g_Stp + ((size_t)ks * BB + b) * CC * CC;

    #pragma unroll
    for (int mi = 0; mi < 4; mi++)
        #pragma unroll
        for (int h = 0; h < 2; h++) {
            const int rr = rbase + mi * 16 + 8 * h;
            #pragma unroll
            for (int ni = 0; ni < 4; ni++) {
                float2 v;
                v.x = acc[mi][ni][2 * h + 0];
                v.y = acc[mi][ni][2 * h + 1];
                *(float2*)(Sp + (size_t)rr * CC + cbase + ni * 8) = v;
            }
        }
}

// ---------------- reduce slabs (float4) ----------------
__global__ void k_sum()
{
    const size_t i = ((size_t)blockIdx.x * 256 + threadIdx.x) * 4;
    const size_t STRIDE = (size_t)BB * CC * CC;
    float4 s = make_float4(0.f, 0.f, 0.f, 0.f);
    #pragma unroll
    for (int ks = 0; ks < KSPLIT; ks++) {
        float4 v = *(const float4*)(g_Stp + ks * STRIDE + i);
        s.x += v.x; s.y += v.y; s.z += v.z; s.w += v.w;
    }
    *(float4*)(g_St + i) = s;
}

// ---------------- prep: split x to bf16 hi/lo ----------------
__global__ void k_prep_x(const float* __restrict__ x)
{
    const size_t i = (size_t)blockIdx.x * 256 + threadIdx.x;
    float4 f = ((const float4*)x)[i];
    uint32_t l0, l1;
    uint32_t h0 = pack2(f.x, f.y, l0);
    uint32_t h1 = pack2(f.z, f.w, l1);
    *(uint2*)(g_xh + 4 * i) = make_uint2(h0, h1);
    *(uint2*)(g_xl + 4 * i) = make_uint2(l0, l1);
}

// ---------------- fp32 64x64 core for small middle GEMMs ----------------
// BSCALE: B row k scaled by 1/bscale[k] (reciprocal computed inline)
template<bool BSCALE>
__device__ __forceinline__ void core64(
    const float* __restrict__ A, int lda,
    const float* __restrict__ B, int ldb,
    const float* __restrict__ bscale, float acc[4][4])
{
    __shared__ __align__(16) float As[16][68];
    __shared__ __align__(16) float Bs[16][68];
    const int t = threadIdx.x, tx = t & 15, ty = t >> 4;

    for (int k0 = 0; k0 < CC; k0 += 16) {
        __syncthreads();
        {
            const int r = t >> 2, q = t & 3;
            float4 a4 = *(const float4*)(A + (size_t)r * lda + k0 + 4 * q);
            As[4*q+0][r] = a4.x; As[4*q+1][r] = a4.y; As[4*q+2][r] = a4.z; As[4*q+3][r] = a4.w;
            const int kr = t >> 4, c0 = (t & 15) * 4;
            float4 b4 = *(const float4*)(B + (size_t)(k0 + kr) * ldb + c0);
            if (BSCALE) {
                float s = 1.0f / bscale[k0 + kr];
                b4.x *= s; b4.y *= s; b4.z *= s; b4.w *= s;
            }
            *(float4*)&Bs[kr][c0] = b4;
        }
        __syncthreads();
        #pragma unroll
        for (int k = 0; k < 16; k++) {
            float4 a4 = *(const float4*)&As[k][ty * 4];
            float4 b4 = *(const float4*)&Bs[k][tx * 4];
            float av[4] = {a4.x, a4.y, a4.z, a4.w};
            float bv[4] = {b4.x, b4.y, b4.z, b4.w};
            #pragma unroll
            for (int i = 0; i < 4; i++)
                #pragma unroll
                for (int j = 0; j < 4; j++)
                    acc[i][j] += av[i] * bv[j];
        }
    }
}

// ---- K0: W2 = w_proj @ Wv; ALSO splits Wk to bf16 hi/lo + zeroes rowsum ----
__global__ void __launch_bounds__(256)
k_w2(const float* __restrict__ w_proj, const float* __restrict__ w_qkv)
{
    // fused prep: 16 blocks x 256 threads = 4096 threads cover Wk (65536) + rowsum (2048)
    const int gt = (blockIdx.y * 4 + blockIdx.x) * 256 + threadIdx.x;
    #pragma unroll
    for (int i = 0; i < 16; i++) {
        const int idx = gt + i * 4096;
        float v = w_qkv[CC * CC + idx];
        __nv_bfloat16 h = __float2bfloat16(v);
        g_Wkh[idx] = h;
        g_Wkl[idx] = __float2bfloat16(v - __bfloat162float(h));
    }
    if (gt < BB * CC) g_rowsum[gt] = 0.f;

    const int m0 = blockIdx.y * 64, n0 = blockIdx.x * 64;
    float acc[4][4] = {};
    core64<false>(w_proj + (size_t)m0 * CC, CC,
                  w_qkv + (size_t)2 * CC * CC + n0, CC, nullptr, acc);
    const int tx = threadIdx.x & 15, ty = threadIdx.x >> 4;
    #pragma unroll
    for (int i = 0; i < 4; i++)
        #pragma unroll
        for (int j = 0; j < 4; j++)
            g_W2[(m0 + ty * 4 + i) * CC + n0 + tx * 4 + j] = acc[i][j];
}

__global__ void __launch_bounds__(256)
k_r(const float* __restrict__ w_qkv)
{
    const int b = blockIdx.z, m0 = blockIdx.y * 64, n0 = blockIdx.x * 64;
    float acc[4][4] = {};
    core64<true>(g_St + (size_t)b * CC * CC + (size_t)m0 * CC, CC,
                 w_qkv + n0, CC, g_rowsum + b * CC, acc);
    const int tx = threadIdx.x & 15, ty = threadIdx.x >> 4;
    float* Rb = g_R + (size_t)b * CC * CC;
    #pragma unroll
    for (int i = 0; i < 4; i++)
        #pragma unroll
        for (int j = 0; j < 4; j++)
            Rb[(m0 + ty * 4 + i) * CC + n0 + tx * 4 + j] = acc[i][j];
}

__global__ void __launch_bounds__(256)
k_m(const float* __restrict__ gamma, const float* __restrict__ var)
{
    const int b = blockIdx.z, m0 = blockIdx.y * 64, n0 = blockIdx.x * 64;
    float acc[4][4] = {};
    core64<false>(g_W2 + (size_t)m0 * CC, CC,
                  g_R + (size_t)b * CC * CC + n0, CC, nullptr, acc);
    const int tx = threadIdx.x & 15, ty = threadIdx.x >> 4;
    __nv_bfloat16* Mh = g_Mh + (size_t)b * CC * CC;
    __nv_bfloat16* Ml = g_Ml + (size_t)b * CC * CC;
    #pragma unroll
    for (int i = 0; i < 4; i++) {
        const int o = m0 + ty * 4 + i;
        const float inv = gamma[o] * rsqrtf(var[o] + EPS);
        #pragma unroll
        for (int j = 0; j < 4; j++) {
            float v = inv * acc[i][j];
            __nv_bfloat16 h = __float2bfloat16(v);
            Mh[o * CC + n0 + tx * 4 + j] = h;
            Ml[o * CC + n0 + tx * 4 + j] = __float2bfloat16(v - __bfloat162float(h));
        }
    }
}

// ---------------- launch ----------------
extern "C" void kernel_launch(void* const* d_in, const int* in_sizes, int n_in,
                              void* d_out, int out_size)
{
    const float* x      = (const float*)d_in[0];
    const float* w_qkv  = (const float*)d_in[1];
    const float* w_proj = (const float*)d_in[2];
    const float* gamma  = (const float*)d_in[3];
    const float* beta   = (const float*)d_in[4];
    const float* mean   = (const float*)d_in[5];
    const float* var    = (const float*)d_in[6];
    float* out = (float*)d_out;

    cudaFuncSetAttribute(k_exp, cudaFuncAttributeMaxDynamicSharedMemorySize, NN_SMEM);
    cudaFuncSetAttribute(k_out, cudaFuncAttributeMaxDynamicSharedMemorySize, NN_SMEM);
    cudaFuncSetAttribute(k_st,  cudaFuncAttributeMaxDynamicSharedMemorySize, NT_SMEM);

    dim3 blk(256);
    k_prep_x<<<dim3((size_t)BB * CC * NSP / 1024), blk>>>(x);
    k_w2<<<dim3(4, 4), blk>>>(w_proj, w_qkv);    // + Wk split + rowsum zero
    k_exp<<<dim3(NSP / 128, 2, BB), blk, NN_SMEM>>>();
    k_st<<<dim3(2, 2, BB * KSPLIT), blk, NT_SMEM>>>();
    k_sum<<<dim3(BB * CC * CC / 1024), blk>>>();
    k_r<<<dim3(4, 4, BB), blk>>>(w_qkv);
    k_m<<<dim3(4, 4, BB), blk>>>(gamma, var);
    k_out<<<dim3(NSP / 128, 2, BB), blk, NN_SMEM>>>(gamma, beta, mean, var, out);
}

// round 15
// speedup vs baseline: 1.0991x; 1.0128x over previous
#include <cuda_runtime.h>
#include <cuda_bf16.h>
#include <math.h>
#include <stdint.h>

#define CC   256
#define NSP  16384
#define BB   8
#define EPS  1e-5f
#define KSPLIT 8

// ---------------- scratch (device globals) ----------------
__device__ __nv_bfloat16 g_xh[(size_t)BB * CC * NSP], g_xl[(size_t)BB * CC * NSP];
__device__ __nv_bfloat16 g_Eh[(size_t)BB * CC * NSP], g_El[(size_t)BB * CC * NSP];
__device__ float g_rowsum[BB * CC];
__device__ float g_Stp[(size_t)KSPLIT * BB * CC * CC];
__device__ float g_St[BB * CC * CC];
__device__ float g_R[BB * CC * CC];
__device__ float g_W2[CC * CC];
__device__ __nv_bfloat16 g_Wkh[CC * CC], g_Wkl[CC * CC];
__device__ __nv_bfloat16 g_Mh[BB * CC * CC], g_Ml[BB * CC * CC];

// ---------------- smem stage layouts ----------------
// NN kernels (k_exp/k_out): A [128][40] hi/lo + B(x^T) [32][136] hi/lo, 3-stage
#define NN_AH 0
#define NN_AL 10240
#define NN_BH 20480
#define NN_BL 29184
#define NN_STG 37888
#define NN_SMEM (3 * NN_STG)    // 113664 -> 2 CTAs/SM
// NT kernel (k_st): A,B both [128][40] hi/lo, 2-stage
#define NT_AH 0
#define NT_AL 10240
#define NT_BH 20480
#define NT_BL 30720
#define NT_STG 40960
#define NT_SMEM (2 * NT_STG)    // 81920 -> 2 CTAs/SM

// ---------------- helpers ----------------
__device__ __forceinline__ uint32_t smem_u32(const void* p) {
    uint32_t a;
    asm("{ .reg .u64 t; cvta.to.shared.u64 t, %1; cvt.u32.u64 %0, t; }" : "=r"(a) : "l"(p));
    return a;
}
__device__ __forceinline__ void cpa16(uint32_t dst, const void* src) {
    asm volatile("cp.async.cg.shared.global [%0], [%1], 16;" :: "r"(dst), "l"(src));
}
#define CP_COMMIT()  asm volatile("cp.async.commit_group;")
#define CP_WAIT(n)   asm volatile("cp.async.wait_group %0;" :: "n"(n))

__device__ __forceinline__ void ldm4(uint32_t* r, const void* p) {
    uint32_t a = (uint32_t)__cvta_generic_to_shared(p);
    asm volatile("ldmatrix.sync.aligned.m8n8.x4.shared.b16 {%0,%1,%2,%3},[%4];"
                 : "=r"(r[0]), "=r"(r[1]), "=r"(r[2]), "=r"(r[3]) : "r"(a));
}
__device__ __forceinline__ void ldm2(uint32_t* r, const void* p) {
    uint32_t a = (uint32_t)__cvta_generic_to_shared(p);
    asm volatile("ldmatrix.sync.aligned.m8n8.x2.shared.b16 {%0,%1},[%2];"
                 : "=r"(r[0]), "=r"(r[1]) : "r"(a));
}
__device__ __forceinline__ void ldm2t(uint32_t* r, const void* p) {
    uint32_t a = (uint32_t)__cvta_generic_to_shared(p);
    asm volatile("ldmatrix.sync.aligned.m8n8.x2.trans.shared.b16 {%0,%1},[%2];"
                 : "=r"(r[0]), "=r"(r[1]) : "r"(a));
}
__device__ __forceinline__ void mma_bf(float* d, const uint32_t* a, const uint32_t* b) {
    asm volatile("mma.sync.aligned.m16n8k16.row.col.f32.bf16.bf16.f32 "
                 "{%0,%1,%2,%3},{%4,%5,%6,%7},{%8,%9},{%0,%1,%2,%3};"
                 : "+f"(d[0]), "+f"(d[1]), "+f"(d[2]), "+f"(d[3])
                 : "r"(a[0]), "r"(a[1]), "r"(a[2]), "r"(a[3]), "r"(b[0]), "r"(b[1]));
}
__device__ __forceinline__ uint32_t pack2(float a, float b, uint32_t& lo) {
    __nv_bfloat16 ha = __float2bfloat16(a), hb = __float2bfloat16(b);
    __nv_bfloat16 la = __float2bfloat16(a - __bfloat162float(ha));
    __nv_bfloat16 lb = __float2bfloat16(b - __bfloat162float(hb));
    lo = (uint32_t)__bfloat16_as_ushort(la) | ((uint32_t)__bfloat16_as_ushort(lb) << 16);
    return (uint32_t)__bfloat16_as_ushort(ha) | ((uint32_t)__bfloat16_as_ushort(hb) << 16);
}

// ---------------- staging via cp.async ----------------
__device__ __forceinline__ void stageR(uint32_t dh, uint32_t dl,
    const __nv_bfloat16* __restrict__ gh, const __nv_bfloat16* __restrict__ gl,
    size_t stride)
{
    const int r = threadIdx.x >> 1, p = threadIdx.x & 1;
    const char* s0 = (const char*)(gh + (size_t)r * stride) + p * 32;
    const char* s1 = (const char*)(gl + (size_t)r * stride) + p * 32;
    const uint32_t o = r * 80 + p * 32;
    cpa16(dh + o, s0); cpa16(dh + o + 16, s0 + 16);
    cpa16(dl + o, s1); cpa16(dl + o + 16, s1 + 16);
}
__device__ __forceinline__ void stageB(uint32_t dh, uint32_t dl,
    const __nv_bfloat16* __restrict__ gh, const __nv_bfloat16* __restrict__ gl,
    size_t stride)
{
    const int k = threadIdx.x >> 3, seg = threadIdx.x & 7;
    const char* s0 = (const char*)(gh + (size_t)k * stride) + seg * 32;
    const char* s1 = (const char*)(gl + (size_t)k * stride) + seg * 32;
    const uint32_t o = k * 272 + seg * 32;
    cpa16(dh + o, s0); cpa16(dh + o + 16, s0 + 16);
    cpa16(dl + o, s1); cpa16(dl + o + 16, s1 + 16);
}

// ---------------- mma compute for one 32-K chunk (A-frag reuse) -------------
template<bool BT>
__device__ __forceinline__ void compute32(const char* smb, float acc[4][4][4])
{
    const int t = threadIdx.x, lane = t & 31, w = t >> 5;
    const int wm = w & 1, wn = w >> 1;
    const int ar = wm * 64 + (lane & 15);
    const int ac = (lane >> 4) * 8;
    const int btr = lane & 15;
    const int btc = wn * 32;
    const int nr = wn * 32 + (lane & 7);
    const int nc = ((lane >> 3) & 1) * 8;

    const __nv_bfloat16* Ah = (const __nv_bfloat16*)(smb + (BT ? NN_AH : NT_AH));
    const __nv_bfloat16* Al = (const __nv_bfloat16*)(smb + (BT ? NN_AL : NT_AL));
    const __nv_bfloat16* Bh = (const __nv_bfloat16*)(smb + (BT ? NN_BH : NT_BH));
    const __nv_bfloat16* Bl = (const __nv_bfloat16*)(smb + (BT ? NN_BL : NT_BL));

    #pragma unroll
    for (int kk = 0; kk < 2; kk++) {
        uint32_t ah[4][4], al[4][4], bq[4][2];
        #pragma unroll
        for (int mi = 0; mi < 4; mi++) {
            ldm4(ah[mi], Ah + (ar + mi * 16) * 40 + kk * 16 + ac);
            ldm4(al[mi], Al + (ar + mi * 16) * 40 + kk * 16 + ac);
        }
        #pragma unroll
        for (int ni = 0; ni < 4; ni++) {
            if (BT) ldm2t(bq[ni], Bh + (kk * 16 + btr) * 136 + btc + ni * 8);
            else    ldm2 (bq[ni], Bh + (nr + ni * 8) * 40 + kk * 16 + nc);
        }
        #pragma unroll
        for (int mi = 0; mi < 4; mi++)
            #pragma unroll
            for (int ni = 0; ni < 4; ni++)
                mma_bf(acc[mi][ni], ah[mi], bq[ni]);
        #pragma unroll
        for (int mi = 0; mi < 4; mi++)
            #pragma unroll
            for (int ni = 0; ni < 4; ni++)
                mma_bf(acc[mi][ni], al[mi], bq[ni]);
        #pragma unroll
        for (int ni = 0; ni < 4; ni++) {
            if (BT) ldm2t(bq[ni], Bl + (kk * 16 + btr) * 136 + btc + ni * 8);
            else    ldm2 (bq[ni], Bl + (nr + ni * 8) * 40 + kk * 16 + nc);
        }
        #pragma unroll
        for (int mi = 0; mi < 4; mi++)
            #pragma unroll
            for (int ni = 0; ni < 4; ni++)
                mma_bf(acc[mi][ni], ah[mi], bq[ni]);
    }
}

#define ACC_ZERO(acc) { \
    _Pragma("unroll") for (int _a = 0; _a < 4; _a++) \
    _Pragma("unroll") for (int _c = 0; _c < 4; _c++) \
    _Pragma("unroll") for (int _d = 0; _d < 4; _d++) acc[_a][_c][_d] = 0.f; }

// 3-stage, 1-sync mainloop for NN kernels (8 chunks of K=32)
#define NN_MAINLOOP(Agh, Agl, Bgh, Bgl) { \
    stageR(sb + NN_AH, sb + NN_AL, Agh, Agl, CC); \
    stageB(sb + NN_BH, sb + NN_BL, Bgh, Bgl, NSP); \
    CP_COMMIT(); \
    stageR(sb + NN_STG + NN_AH, sb + NN_STG + NN_AL, Agh + 32, Agl + 32, CC); \
    stageB(sb + NN_STG + NN_BH, sb + NN_STG + NN_BL, \
           Bgh + (size_t)32 * NSP, Bgl + (size_t)32 * NSP, NSP); \
    CP_COMMIT(); \
    _Pragma("unroll 1") \
    for (int ch = 0; ch < 8; ch++) { \
        if (ch < 7) { CP_WAIT(1); } else { CP_WAIT(0); } \
        __syncthreads(); \
        if (ch + 2 < 8) { \
            const int kn = (ch + 2) * 32; \
            const uint32_t bb = sb + ((ch + 2) % 3) * NN_STG; \
            stageR(bb + NN_AH, bb + NN_AL, Agh + kn, Agl + kn, CC); \
            stageB(bb + NN_BH, bb + NN_BL, \
                   Bgh + (size_t)kn * NSP, Bgl + (size_t)kn * NSP, NSP); \
            CP_COMMIT(); \
        } \
        compute32<true>(sm + (ch % 3) * NN_STG, acc); \
    } }

// ---------------- K1: E = exp(Wk @ x) + rowsums ----------------
__global__ void __launch_bounds__(256, 2)
k_exp()
{
    extern __shared__ char sm[];
    const uint32_t sb = smem_u32(sm);
    const int b = blockIdx.z, m0 = blockIdx.y * 128, n0 = blockIdx.x * 128;

    const __nv_bfloat16* Agh = g_Wkh + (size_t)m0 * CC;
    const __nv_bfloat16* Agl = g_Wkl + (size_t)m0 * CC;
    const __nv_bfloat16* Bgh = g_xh + (size_t)b * CC * NSP + n0;
    const __nv_bfloat16* Bgl = g_xl + (size_t)b * CC * NSP + n0;

    float acc[4][4][4]; ACC_ZERO(acc);
    NN_MAINLOOP(Agh, Agl, Bgh, Bgl);

    const int t = threadIdx.x, lane = t & 31, w = t >> 5;
    const int wm = w & 1, wn = w >> 1;
    const int rbase = m0 + wm * 64 + (lane >> 2);
    const int cbase = n0 + wn * 32 + (lane & 3) * 2;
    __nv_bfloat16* Eh = g_Eh + (size_t)b * CC * NSP;
    __nv_bfloat16* El = g_El + (size_t)b * CC * NSP;

    float rs[8] = {0, 0, 0, 0, 0, 0, 0, 0};
    #pragma unroll
    for (int mi = 0; mi < 4; mi++)
        #pragma unroll
        for (int h = 0; h < 2; h++) {
            const int rr = rbase + mi * 16 + 8 * h;
            #pragma unroll
            for (int ni = 0; ni < 4; ni++) {
                float e0 = __expf(acc[mi][ni][2 * h + 0]);
                float e1 = __expf(acc[mi][ni][2 * h + 1]);
                rs[mi * 2 + h] += e0 + e1;
                uint32_t lp, hp = pack2(e0, e1, lp);
                const size_t off = (size_t)rr * NSP + cbase + ni * 8;
                *(uint32_t*)(Eh + off) = hp;
                *(uint32_t*)(El + off) = lp;
            }
        }
    #pragma unroll
    for (int i = 0; i < 8; i++) {
        float v = rs[i];
        v += __shfl_xor_sync(0xffffffffu, v, 1);
        v += __shfl_xor_sync(0xffffffffu, v, 2);
        if ((lane & 3) == 0) {
            const int rr = rbase + (i >> 1) * 16 + 8 * (i & 1);
            atomicAdd(&g_rowsum[b * CC + rr], v);
        }
    }
}

// ---------------- K5: out = relu(M @ x + bias) ----------------
__global__ void __launch_bounds__(256, 2)
k_out(const float* __restrict__ gamma, const float* __restrict__ beta,
      const float* __restrict__ mean,  const float* __restrict__ var,
      float* __restrict__ out)
{
    extern __shared__ char sm[];
    const uint32_t sb = smem_u32(sm);
    const int b = blockIdx.z, m0 = blockIdx.y * 128, n0 = blockIdx.x * 128;

    const __nv_bfloat16* Agh = g_Mh + (size_t)b * CC * CC + (size_t)m0 * CC;
    const __nv_bfloat16* Agl = g_Ml + (size_t)b * CC * CC + (size_t)m0 * CC;
    const __nv_bfloat16* Bgh = g_xh + (size_t)b * CC * NSP + n0;
    const __nv_bfloat16* Bgl = g_xl + (size_t)b * CC * NSP + n0;

    float acc[4][4][4]; ACC_ZERO(acc);
    NN_MAINLOOP(Agh, Agl, Bgh, Bgl);

    const int t = threadIdx.x, lane = t & 31, w = t >> 5;
    const int wm = w & 1, wn = w >> 1;
    const int rbase = m0 + wm * 64 + (lane >> 2);
    const int cbase = n0 + wn * 32 + (lane & 3) * 2;
    float* Ob = out + (size_t)b * CC * NSP;

    #pragma unroll
    for (int mi = 0; mi < 4; mi++)
        #pragma unroll
        for (int h = 0; h < 2; h++) {
            const int o = rbase + mi * 16 + 8 * h;
            const float inv  = gamma[o] * rsqrtf(var[o] + EPS);
            const float bias = beta[o] - mean[o] * inv;
            #pragma unroll
            for (int ni = 0; ni < 4; ni++) {
                float2 v;
                v.x = fmaxf(acc[mi][ni][2 * h + 0] + bias, 0.f);
                v.y = fmaxf(acc[mi][ni][2 * h + 1] + bias, 0.f);
                *(float2*)(Ob + (size_t)o * NSP + cbase + ni * 8) = v;
            }
        }
}

// ---------- K2: St partial slabs (atomic-free, 2-stage, ONE sync/chunk) -----
__global__ void __launch_bounds__(256, 2)
k_st()
{
    extern __shared__ char sm[];
    const uint32_t sb = smem_u32(sm);
    const int c0 = blockIdx.x * 128, e0 = blockIdx.y * 128;
    const int b = blockIdx.z >> 3, ks = blockIdx.z & 7;
    const int kbeg = ks * (NSP / KSPLIT);     // 2048 per split
    const int NCH = (NSP / KSPLIT) / 32;      // 64 chunks

    const __nv_bfloat16* Agh = g_xh + (size_t)(b * CC + e0) * NSP + kbeg;
    const __nv_bfloat16* Agl = g_xl + (size_t)(b * CC + e0) * NSP + kbeg;
    const __nv_bfloat16* Bgh = g_Eh + (size_t)(b * CC + c0) * NSP + kbeg;
    const __nv_bfloat16* Bgl = g_El + (size_t)(b * CC + c0) * NSP + kbeg;

    float acc[4][4][4]; ACC_ZERO(acc);

    stageR(sb + NT_AH, sb + NT_AL, Agh, Agl, NSP);
    stageR(sb + NT_BH, sb + NT_BL, Bgh, Bgl, NSP);
    CP_COMMIT();
    #pragma unroll 1
    for (int ch = 0; ch < NCH; ch++) {
        CP_WAIT(0);
        __syncthreads();
        if (ch + 1 < NCH) {
            const int kn = (ch + 1) * 32;
            const uint32_t bb = sb + ((ch + 1) & 1) * NT_STG;
            stageR(bb + NT_AH, bb + NT_AL, Agh + kn, Agl + kn, NSP);
            stageR(bb + NT_BH, bb + NT_BL, Bgh + kn, Bgl + kn, NSP);
            CP_COMMIT();
        }
        compute32<false>(sm + (ch & 1) * NT_STG, acc);
    }

    const int t = threadIdx.x, lane = t & 31, w = t >> 5;
    const int wm = w & 1, wn = w >> 1;
    const int rbase = e0 + wm * 64 + (lane >> 2);
    const int cbase = c0 + wn * 32 + (lane & 3) * 2;
    float* Sp = g_Stp + ((size_t)ks * BB + b) * CC * CC;

    #pragma unroll
    for (int mi = 0; mi < 4; mi++)
        #pragma unroll
        for (int h = 0; h < 2; h++) {
            const int rr = rbase + mi * 16 + 8 * h;
            #pragma unroll
            for (int ni = 0; ni < 4; ni++) {
                float2 v;
                v.x = acc[mi][ni][2 * h + 0];
                v.y = acc[mi][ni][2 * h + 1];
                *(float2*)(Sp + (size_t)rr * CC + cbase + ni * 8) = v;
            }
        }
}

// ---------------- reduce slabs (float4) ----------------
__global__ void k_sum()
{
    const size_t i = ((size_t)blockIdx.x * 256 + threadIdx.x) * 4;
    const size_t STRIDE = (size_t)BB * CC * CC;
    float4 s = make_float4(0.f, 0.f, 0.f, 0.f);
    #pragma unroll
    for (int ks = 0; ks < KSPLIT; ks++) {
        float4 v = *(const float4*)(g_Stp + ks * STRIDE + i);
        s.x += v.x; s.y += v.y; s.z += v.z; s.w += v.w;
    }
    *(float4*)(g_St + i) = s;
}

// ---------------- fp32 64x64 core for small middle GEMMs ----------------
// BSCALE: B row k scaled by 1/bscale[k] (reciprocal computed inline)
template<bool BSCALE>
__device__ __forceinline__ void core64(
    const float* __restrict__ A, int lda,
    const float* __restrict__ B, int ldb,
    const float* __restrict__ bscale, float acc[4][4])
{
    __shared__ __align__(16) float As[16][68];
    __shared__ __align__(16) float Bs[16][68];
    const int t = threadIdx.x, tx = t & 15, ty = t >> 4;

    for (int k0 = 0; k0 < CC; k0 += 16) {
        __syncthreads();
        {
            const int r = t >> 2, q = t & 3;
            float4 a4 = *(const float4*)(A + (size_t)r * lda + k0 + 4 * q);
            As[4*q+0][r] = a4.x; As[4*q+1][r] = a4.y; As[4*q+2][r] = a4.z; As[4*q+3][r] = a4.w;
            const int kr = t >> 4, c0 = (t & 15) * 4;
            float4 b4 = *(const float4*)(B + (size_t)(k0 + kr) * ldb + c0);
            if (BSCALE) {
                float s = 1.0f / bscale[k0 + kr];
                b4.x *= s; b4.y *= s; b4.z *= s; b4.w *= s;
            }
            *(float4*)&Bs[kr][c0] = b4;
        }
        __syncthreads();
        #pragma unroll
        for (int k = 0; k < 16; k++) {
            float4 a4 = *(const float4*)&As[k][ty * 4];
            float4 b4 = *(const float4*)&Bs[k][tx * 4];
            float av[4] = {a4.x, a4.y, a4.z, a4.w};
            float bv[4] = {b4.x, b4.y, b4.z, b4.w};
            #pragma unroll
            for (int i = 0; i < 4; i++)
                #pragma unroll
                for (int j = 0; j < 4; j++)
                    acc[i][j] += av[i] * bv[j];
        }
    }
}

// ---- K0 (fused init): blocks 0..15 -> W2 GEMM + Wk split + rowsum zero;
//      blocks 16..  -> x split to bf16 hi/lo ----
__global__ void __launch_bounds__(256)
k_init(const float* __restrict__ x,
       const float* __restrict__ w_proj, const float* __restrict__ w_qkv)
{
    if (blockIdx.x >= 16) {
        // x split: one float4 per thread
        const size_t i = (size_t)(blockIdx.x - 16) * 256 + threadIdx.x;
        float4 f = ((const float4*)x)[i];
        uint32_t l0, l1;
        uint32_t h0 = pack2(f.x, f.y, l0);
        uint32_t h1 = pack2(f.z, f.w, l1);
        *(uint2*)(g_xh + 4 * i) = make_uint2(h0, h1);
        *(uint2*)(g_xl + 4 * i) = make_uint2(l0, l1);
        return;
    }
    // --- W2 block path ---
    const int gt = blockIdx.x * 256 + threadIdx.x;   // 0..4095
    #pragma unroll
    for (int i = 0; i < 16; i++) {
        const int idx = gt + i * 4096;
        float v = w_qkv[CC * CC + idx];
        __nv_bfloat16 h = __float2bfloat16(v);
        g_Wkh[idx] = h;
        g_Wkl[idx] = __float2bfloat16(v - __bfloat162float(h));
    }
    if (gt < BB * CC) g_rowsum[gt] = 0.f;

    const int m0 = (blockIdx.x >> 2) * 64, n0 = (blockIdx.x & 3) * 64;
    float acc[4][4] = {};
    core64<false>(w_proj + (size_t)m0 * CC, CC,
                  w_qkv + (size_t)2 * CC * CC + n0, CC, nullptr, acc);
    const int tx = threadIdx.x & 15, ty = threadIdx.x >> 4;
    #pragma unroll
    for (int i = 0; i < 4; i++)
        #pragma unroll
        for (int j = 0; j < 4; j++)
            g_W2[(m0 + ty * 4 + i) * CC + n0 + tx * 4 + j] = acc[i][j];
}

__global__ void __launch_bounds__(256)
k_r(const float* __restrict__ w_qkv)
{
    const int b = blockIdx.z, m0 = blockIdx.y * 64, n0 = blockIdx.x * 64;
    float acc[4][4] = {};
    core64<true>(g_St + (size_t)b * CC * CC + (size_t)m0 * CC, CC,
                 w_qkv + n0, CC, g_rowsum + b * CC, acc);
    const int tx = threadIdx.x & 15, ty = threadIdx.x >> 4;
    float* Rb = g_R + (size_t)b * CC * CC;
    #pragma unroll
    for (int i = 0; i < 4; i++)
        #pragma unroll
        for (int j = 0; j < 4; j++)
            Rb[(m0 + ty * 4 + i) * CC + n0 + tx * 4 + j] = acc[i][j];
}

__global__ void __launch_bounds__(256)
k_m(const float* __restrict__ gamma, const float* __restrict__ var)
{
    const int b = blockIdx.z, m0 = blockIdx.y * 64, n0 = blockIdx.x * 64;
    float acc[4][4] = {};
    core64<false>(g_W2 + (size_t)m0 * CC, CC,
                  g_R + (size_t)b * CC * CC + n0, CC, nullptr, acc);
    const int tx = threadIdx.x & 15, ty = threadIdx.x >> 4;
    __nv_bfloat16* Mh = g_Mh + (size_t)b * CC * CC;
    __nv_bfloat16* Ml = g_Ml + (size_t)b * CC * CC;
    #pragma unroll
    for (int i = 0; i < 4; i++) {
        const int o = m0 + ty * 4 + i;
        const float inv = gamma[o] * rsqrtf(var[o] + EPS);
        #pragma unroll
        for (int j = 0; j < 4; j++) {
            float v = inv * acc[i][j];
            __nv_bfloat16 h = __float2bfloat16(v);
            Mh[o * CC + n0 + tx * 4 + j] = h;
            Ml[o * CC + n0 + tx * 4 + j] = __float2bfloat16(v - __bfloat162float(h));
        }
    }
}

// ---------------- launch ----------------
extern "C" void kernel_launch(void* const* d_in, const int* in_sizes, int n_in,
                              void* d_out, int out_size)
{
    const float* x      = (const float*)d_in[0];
    const float* w_qkv  = (const float*)d_in[1];
    const float* w_proj = (const float*)d_in[2];
    const float* gamma  = (const float*)d_in[3];
    const float* beta   = (const float*)d_in[4];
    const float* mean   = (const float*)d_in[5];
    const float* var    = (const float*)d_in[6];
    float* out = (float*)d_out;

    cudaFuncSetAttribute(k_exp, cudaFuncAttributeMaxDynamicSharedMemorySize, NN_SMEM);
    cudaFuncSetAttribute(k_out, cudaFuncAttributeMaxDynamicSharedMemorySize, NN_SMEM);
    cudaFuncSetAttribute(k_st,  cudaFuncAttributeMaxDynamicSharedMemorySize, NT_SMEM);

    dim3 blk(256);
    // fused: x split (32768 blocks) + W2 GEMM/Wk split/rowsum zero (16 blocks)
    k_init<<<dim3(16 + (size_t)BB * CC * NSP / 1024), blk>>>(x, w_proj, w_qkv);
    k_exp<<<dim3(NSP / 128, 2, BB), blk, NN_SMEM>>>();
    k_st<<<dim3(2, 2, BB * KSPLIT), blk, NT_SMEM>>>();
    k_sum<<<dim3(BB * CC * CC / 1024), blk>>>();
    k_r<<<dim3(4, 4, BB), blk>>>(w_qkv);
    k_m<<<dim3(4, 4, BB), blk>>>(gamma, var);
    k_out<<<dim3(NSP / 128, 2, BB), blk, NN_SMEM>>>(gamma, beta, mean, var, out);
}

// round 16
// speedup vs baseline: 1.1019x; 1.0026x over previous
#include <cuda_runtime.h>
#include <cuda_bf16.h>
#include <math.h>
#include <stdint.h>

#define CC   256
#define NSP  16384
#define BB   8
#define EPS  1e-5f
#define KSPLIT 8

// ---------------- scratch (device globals) ----------------
__device__ __nv_bfloat16 g_xh[(size_t)BB * CC * NSP], g_xl[(size_t)BB * CC * NSP];
__device__ __nv_bfloat16 g_Eh[(size_t)BB * CC * NSP], g_El[(size_t)BB * CC * NSP];
__device__ float g_rowsum[BB * CC];
__device__ float g_St[BB * CC * CC];
__device__ float g_R[BB * CC * CC];
__device__ float g_W2[CC * CC];
__device__ __nv_bfloat16 g_Wkh[CC * CC], g_Wkl[CC * CC];
__device__ __nv_bfloat16 g_Mh[BB * CC * CC], g_Ml[BB * CC * CC];

// ---------------- smem stage layouts ----------------
// NN kernels (k_exp/k_out): A [128][40] hi/lo + B(x^T) [32][136] hi/lo, 3-stage
#define NN_AH 0
#define NN_AL 10240
#define NN_BH 20480
#define NN_BL 29184
#define NN_STG 37888
#define NN_SMEM (3 * NN_STG)    // 113664 -> 2 CTAs/SM
// NT kernel (k_st): A,B both [128][40] hi/lo, 2-stage
#define NT_AH 0
#define NT_AL 10240
#define NT_BH 20480
#define NT_BL 30720
#define NT_STG 40960
#define NT_SMEM (2 * NT_STG)    // 81920 -> 2 CTAs/SM

// ---------------- helpers ----------------
__device__ __forceinline__ uint32_t smem_u32(const void* p) {
    uint32_t a;
    asm("{ .reg .u64 t; cvta.to.shared.u64 t, %1; cvt.u32.u64 %0, t; }" : "=r"(a) : "l"(p));
    return a;
}
__device__ __forceinline__ void cpa16(uint32_t dst, const void* src) {
    asm volatile("cp.async.cg.shared.global [%0], [%1], 16;" :: "r"(dst), "l"(src));
}
#define CP_COMMIT()  asm volatile("cp.async.commit_group;")
#define CP_WAIT(n)   asm volatile("cp.async.wait_group %0;" :: "n"(n))

__device__ __forceinline__ void ldm4(uint32_t* r, const void* p) {
    uint32_t a = (uint32_t)__cvta_generic_to_shared(p);
    asm volatile("ldmatrix.sync.aligned.m8n8.x4.shared.b16 {%0,%1,%2,%3},[%4];"
                 : "=r"(r[0]), "=r"(r[1]), "=r"(r[2]), "=r"(r[3]) : "r"(a));
}
__device__ __forceinline__ void ldm2(uint32_t* r, const void* p) {
    uint32_t a = (uint32_t)__cvta_generic_to_shared(p);
    asm volatile("ldmatrix.sync.aligned.m8n8.x2.shared.b16 {%0,%1},[%2];"
                 : "=r"(r[0]), "=r"(r[1]) : "r"(a));
}
__device__ __forceinline__ void ldm2t(uint32_t* r, const void* p) {
    uint32_t a = (uint32_t)__cvta_generic_to_shared(p);
    asm volatile("ldmatrix.sync.aligned.m8n8.x2.trans.shared.b16 {%0,%1},[%2];"
                 : "=r"(r[0]), "=r"(r[1]) : "r"(a));
}
__device__ __forceinline__ void mma_bf(float* d, const uint32_t* a, const uint32_t* b) {
    asm volatile("mma.sync.aligned.m16n8k16.row.col.f32.bf16.bf16.f32 "
                 "{%0,%1,%2,%3},{%4,%5,%6,%7},{%8,%9},{%0,%1,%2,%3};"
                 : "+f"(d[0]), "+f"(d[1]), "+f"(d[2]), "+f"(d[3])
                 : "r"(a[0]), "r"(a[1]), "r"(a[2]), "r"(a[3]), "r"(b[0]), "r"(b[1]));
}
__device__ __forceinline__ uint32_t pack2(float a, float b, uint32_t& lo) {
    __nv_bfloat16 ha = __float2bfloat16(a), hb = __float2bfloat16(b);
    __nv_bfloat16 la = __float2bfloat16(a - __bfloat162float(ha));
    __nv_bfloat16 lb = __float2bfloat16(b - __bfloat162float(hb));
    lo = (uint32_t)__bfloat16_as_ushort(la) | ((uint32_t)__bfloat16_as_ushort(lb) << 16);
    return (uint32_t)__bfloat16_as_ushort(ha) | ((uint32_t)__bfloat16_as_ushort(hb) << 16);
}

// ---------------- staging via cp.async ----------------
__device__ __forceinline__ void stageR(uint32_t dh, uint32_t dl,
    const __nv_bfloat16* __restrict__ gh, const __nv_bfloat16* __restrict__ gl,
    size_t stride)
{
    const int r = threadIdx.x >> 1, p = threadIdx.x & 1;
    const char* s0 = (const char*)(gh + (size_t)r * stride) + p * 32;
    const char* s1 = (const char*)(gl + (size_t)r * stride) + p * 32;
    const uint32_t o = r * 80 + p * 32;
    cpa16(dh + o, s0); cpa16(dh + o + 16, s0 + 16);
    cpa16(dl + o, s1); cpa16(dl + o + 16, s1 + 16);
}
__device__ __forceinline__ void stageB(uint32_t dh, uint32_t dl,
    const __nv_bfloat16* __restrict__ gh, const __nv_bfloat16* __restrict__ gl,
    size_t stride)
{
    const int k = threadIdx.x >> 3, seg = threadIdx.x & 7;
    const char* s0 = (const char*)(gh + (size_t)k * stride) + seg * 32;
    const char* s1 = (const char*)(gl + (size_t)k * stride) + seg * 32;
    const uint32_t o = k * 272 + seg * 32;
    cpa16(dh + o, s0); cpa16(dh + o + 16, s0 + 16);
    cpa16(dl + o, s1); cpa16(dl + o + 16, s1 + 16);
}

// ---------------- mma compute for one 32-K chunk (A-frag reuse) -------------
template<bool BT>
__device__ __forceinline__ void compute32(const char* smb, float acc[4][4][4])
{
    const int t = threadIdx.x, lane = t & 31, w = t >> 5;
    const int wm = w & 1, wn = w >> 1;
    const int ar = wm * 64 + (lane & 15);
    const int ac = (lane >> 4) * 8;
    const int btr = lane & 15;
    const int btc = wn * 32;
    const int nr = wn * 32 + (lane & 7);
    const int nc = ((lane >> 3) & 1) * 8;

    const __nv_bfloat16* Ah = (const __nv_bfloat16*)(smb + (BT ? NN_AH : NT_AH));
    const __nv_bfloat16* Al = (const __nv_bfloat16*)(smb + (BT ? NN_AL : NT_AL));
    const __nv_bfloat16* Bh = (const __nv_bfloat16*)(smb + (BT ? NN_BH : NT_BH));
    const __nv_bfloat16* Bl = (const __nv_bfloat16*)(smb + (BT ? NN_BL : NT_BL));

    #pragma unroll
    for (int kk = 0; kk < 2; kk++) {
        uint32_t ah[4][4], al[4][4], bq[4][2];
        #pragma unroll
        for (int mi = 0; mi < 4; mi++) {
            ldm4(ah[mi], Ah + (ar + mi * 16) * 40 + kk * 16 + ac);
            ldm4(al[mi], Al + (ar + mi * 16) * 40 + kk * 16 + ac);
        }
        #pragma unroll
        for (int ni = 0; ni < 4; ni++) {
            if (BT) ldm2t(bq[ni], Bh + (kk * 16 + btr) * 136 + btc + ni * 8);
            else    ldm2 (bq[ni], Bh + (nr + ni * 8) * 40 + kk * 16 + nc);
        }
        #pragma unroll
        for (int mi = 0; mi < 4; mi++)
            #pragma unroll
            for (int ni = 0; ni < 4; ni++)
                mma_bf(acc[mi][ni], ah[mi], bq[ni]);
        #pragma unroll
        for (int mi = 0; mi < 4; mi++)
            #pragma unroll
            for (int ni = 0; ni < 4; ni++)
                mma_bf(acc[mi][ni], al[mi], bq[ni]);
        #pragma unroll
        for (int ni = 0; ni < 4; ni++) {
            if (BT) ldm2t(bq[ni], Bl + (kk * 16 + btr) * 136 + btc + ni * 8);
            else    ldm2 (bq[ni], Bl + (nr + ni * 8) * 40 + kk * 16 + nc);
        }
        #pragma unroll
        for (int mi = 0; mi < 4; mi++)
            #pragma unroll
            for (int ni = 0; ni < 4; ni++)
                mma_bf(acc[mi][ni], ah[mi], bq[ni]);
    }
}

#define ACC_ZERO(acc) { \
    _Pragma("unroll") for (int _a = 0; _a < 4; _a++) \
    _Pragma("unroll") for (int _c = 0; _c < 4; _c++) \
    _Pragma("unroll") for (int _d = 0; _d < 4; _d++) acc[_a][_c][_d] = 0.f; }

// 3-stage, 1-sync mainloop for NN kernels (8 chunks of K=32)
#define NN_MAINLOOP(Agh, Agl, Bgh, Bgl) { \
    stageR(sb + NN_AH, sb + NN_AL, Agh, Agl, CC); \
    stageB(sb + NN_BH, sb + NN_BL, Bgh, Bgl, NSP); \
    CP_COMMIT(); \
    stageR(sb + NN_STG + NN_AH, sb + NN_STG + NN_AL, Agh + 32, Agl + 32, CC); \
    stageB(sb + NN_STG + NN_BH, sb + NN_STG + NN_BL, \
           Bgh + (size_t)32 * NSP, Bgl + (size_t)32 * NSP, NSP); \
    CP_COMMIT(); \
    _Pragma("unroll 1") \
    for (int ch = 0; ch < 8; ch++) { \
        if (ch < 7) { CP_WAIT(1); } else { CP_WAIT(0); } \
        __syncthreads(); \
        if (ch + 2 < 8) { \
            const int kn = (ch + 2) * 32; \
            const uint32_t bb = sb + ((ch + 2) % 3) * NN_STG; \
            stageR(bb + NN_AH, bb + NN_AL, Agh + kn, Agl + kn, CC); \
            stageB(bb + NN_BH, bb + NN_BL, \
                   Bgh + (size_t)kn * NSP, Bgl + (size_t)kn * NSP, NSP); \
            CP_COMMIT(); \
        } \
        compute32<true>(sm + (ch % 3) * NN_STG, acc); \
    } }

// ---------------- K1: E = exp(Wk @ x) + rowsums ----------------
__global__ void __launch_bounds__(256, 2)
k_exp()
{
    extern __shared__ char sm[];
    const uint32_t sb = smem_u32(sm);
    const int b = blockIdx.z, m0 = blockIdx.y * 128, n0 = blockIdx.x * 128;

    const __nv_bfloat16* Agh = g_Wkh + (size_t)m0 * CC;
    const __nv_bfloat16* Agl = g_Wkl + (size_t)m0 * CC;
    const __nv_bfloat16* Bgh = g_xh + (size_t)b * CC * NSP + n0;
    const __nv_bfloat16* Bgl = g_xl + (size_t)b * CC * NSP + n0;

    float acc[4][4][4]; ACC_ZERO(acc);
    NN_MAINLOOP(Agh, Agl, Bgh, Bgl);

    const int t = threadIdx.x, lane = t & 31, w = t >> 5;
    const int wm = w & 1, wn = w >> 1;
    const int rbase = m0 + wm * 64 + (lane >> 2);
    const int cbase = n0 + wn * 32 + (lane & 3) * 2;
    __nv_bfloat16* Eh = g_Eh + (size_t)b * CC * NSP;
    __nv_bfloat16* El = g_El + (size_t)b * CC * NSP;

    float rs[8] = {0, 0, 0, 0, 0, 0, 0, 0};
    #pragma unroll
    for (int mi = 0; mi < 4; mi++)
        #pragma unroll
        for (int h = 0; h < 2; h++) {
            const int rr = rbase + mi * 16 + 8 * h;
            #pragma unroll
            for (int ni = 0; ni < 4; ni++) {
                float e0 = __expf(acc[mi][ni][2 * h + 0]);
                float e1 = __expf(acc[mi][ni][2 * h + 1]);
                rs[mi * 2 + h] += e0 + e1;
                uint32_t lp, hp = pack2(e0, e1, lp);
                const size_t off = (size_t)rr * NSP + cbase + ni * 8;
                *(uint32_t*)(Eh + off) = hp;
                *(uint32_t*)(El + off) = lp;
            }
        }
    #pragma unroll
    for (int i = 0; i < 8; i++) {
        float v = rs[i];
        v += __shfl_xor_sync(0xffffffffu, v, 1);
        v += __shfl_xor_sync(0xffffffffu, v, 2);
        if ((lane & 3) == 0) {
            const int rr = rbase + (i >> 1) * 16 + 8 * (i & 1);
            atomicAdd(&g_rowsum[b * CC + rr], v);
        }
    }
}

// ---------------- K5: out = relu(M @ x + bias) ----------------
__global__ void __launch_bounds__(256, 2)
k_out(const float* __restrict__ gamma, const float* __restrict__ beta,
      const float* __restrict__ mean,  const float* __restrict__ var,
      float* __restrict__ out)
{
    extern __shared__ char sm[];
    const uint32_t sb = smem_u32(sm);
    const int b = blockIdx.z, m0 = blockIdx.y * 128, n0 = blockIdx.x * 128;

    const __nv_bfloat16* Agh = g_Mh + (size_t)b * CC * CC + (size_t)m0 * CC;
    const __nv_bfloat16* Agl = g_Ml + (size_t)b * CC * CC + (size_t)m0 * CC;
    const __nv_bfloat16* Bgh = g_xh + (size_t)b * CC * NSP + n0;
    const __nv_bfloat16* Bgl = g_xl + (size_t)b * CC * NSP + n0;

    float acc[4][4][4]; ACC_ZERO(acc);
    NN_MAINLOOP(Agh, Agl, Bgh, Bgl);

    const int t = threadIdx.x, lane = t & 31, w = t >> 5;
    const int wm = w & 1, wn = w >> 1;
    const int rbase = m0 + wm * 64 + (lane >> 2);
    const int cbase = n0 + wn * 32 + (lane & 3) * 2;
    float* Ob = out + (size_t)b * CC * NSP;

    #pragma unroll
    for (int mi = 0; mi < 4; mi++)
        #pragma unroll
        for (int h = 0; h < 2; h++) {
            const int o = rbase + mi * 16 + 8 * h;
            const float inv  = gamma[o] * rsqrtf(var[o] + EPS);
            const float bias = beta[o] - mean[o] * inv;
            #pragma unroll
            for (int ni = 0; ni < 4; ni++) {
                float2 v;
                v.x = fmaxf(acc[mi][ni][2 * h + 0] + bias, 0.f);
                v.y = fmaxf(acc[mi][ni][2 * h + 1] + bias, 0.f);
                *(float2*)(Ob + (size_t)o * NSP + cbase + ni * 8) = v;
            }
        }
}

// -- K2: St via direct atomicAdd (no slabs/k_sum), 2-stage, ONE sync/chunk ---
__global__ void __launch_bounds__(256, 2)
k_st()
{
    extern __shared__ char sm[];
    const uint32_t sb = smem_u32(sm);
    const int c0 = blockIdx.x * 128, e0 = blockIdx.y * 128;
    const int b = blockIdx.z >> 3, ks = blockIdx.z & 7;
    const int kbeg = ks * (NSP / KSPLIT);     // 2048 per split
    const int NCH = (NSP / KSPLIT) / 32;      // 64 chunks

    const __nv_bfloat16* Agh = g_xh + (size_t)(b * CC + e0) * NSP + kbeg;
    const __nv_bfloat16* Agl = g_xl + (size_t)(b * CC + e0) * NSP + kbeg;
    const __nv_bfloat16* Bgh = g_Eh + (size_t)(b * CC + c0) * NSP + kbeg;
    const __nv_bfloat16* Bgl = g_El + (size_t)(b * CC + c0) * NSP + kbeg;

    float acc[4][4][4]; ACC_ZERO(acc);

    stageR(sb + NT_AH, sb + NT_AL, Agh, Agl, NSP);
    stageR(sb + NT_BH, sb + NT_BL, Bgh, Bgl, NSP);
    CP_COMMIT();
    #pragma unroll 1
    for (int ch = 0; ch < NCH; ch++) {
        CP_WAIT(0);
        __syncthreads();
        if (ch + 1 < NCH) {
            const int kn = (ch + 1) * 32;
            const uint32_t bb = sb + ((ch + 1) & 1) * NT_STG;
            stageR(bb + NT_AH, bb + NT_AL, Agh + kn, Agl + kn, NSP);
            stageR(bb + NT_BH, bb + NT_BL, Bgh + kn, Bgl + kn, NSP);
            CP_COMMIT();
        }
        compute32<false>(sm + (ch & 1) * NT_STG, acc);
    }

    const int t = threadIdx.x, lane = t & 31, w = t >> 5;
    const int wm = w & 1, wn = w >> 1;
    const int rbase = e0 + wm * 64 + (lane >> 2);
    const int cbase = c0 + wn * 32 + (lane & 3) * 2;
    float* Sb = g_St + (size_t)b * CC * CC;

    #pragma unroll
    for (int mi = 0; mi < 4; mi++)
        #pragma unroll
        for (int h = 0; h < 2; h++) {
            const int rr = rbase + mi * 16 + 8 * h;
            #pragma unroll
            for (int ni = 0; ni < 4; ni++) {
                atomicAdd(&Sb[(size_t)rr * CC + cbase + ni * 8 + 0], acc[mi][ni][2 * h + 0]);
                atomicAdd(&Sb[(size_t)rr * CC + cbase + ni * 8 + 1], acc[mi][ni][2 * h + 1]);
            }
        }
}

// ---------------- fp32 64x64 core for small middle GEMMs ----------------
// BSCALE: B row k scaled by 1/bscale[k] (reciprocal computed inline)
template<bool BSCALE>
__device__ __forceinline__ void core64(
    const float* __restrict__ A, int lda,
    const float* __restrict__ B, int ldb,
    const float* __restrict__ bscale, float acc[4][4])
{
    __shared__ __align__(16) float As[16][68];
    __shared__ __align__(16) float Bs[16][68];
    const int t = threadIdx.x, tx = t & 15, ty = t >> 4;

    for (int k0 = 0; k0 < CC; k0 += 16) {
        __syncthreads();
        {
            const int r = t >> 2, q = t & 3;
            float4 a4 = *(const float4*)(A + (size_t)r * lda + k0 + 4 * q);
            As[4*q+0][r] = a4.x; As[4*q+1][r] = a4.y; As[4*q+2][r] = a4.z; As[4*q+3][r] = a4.w;
            const int kr = t >> 4, c0 = (t & 15) * 4;
            float4 b4 = *(const float4*)(B + (size_t)(k0 + kr) * ldb + c0);
            if (BSCALE) {
                float s = 1.0f / bscale[k0 + kr];
                b4.x *= s; b4.y *= s; b4.z *= s; b4.w *= s;
            }
            *(float4*)&Bs[kr][c0] = b4;
        }
        __syncthreads();
        #pragma unroll
        for (int k = 0; k < 16; k++) {
            float4 a4 = *(const float4*)&As[k][ty * 4];
            float4 b4 = *(const float4*)&Bs[k][tx * 4];
            float av[4] = {a4.x, a4.y, a4.z, a4.w};
            float bv[4] = {b4.x, b4.y, b4.z, b4.w};
            #pragma unroll
            for (int i = 0; i < 4; i++)
                #pragma unroll
                for (int j = 0; j < 4; j++)
                    acc[i][j] += av[i] * bv[j];
        }
    }
}

// ---- K0 (fused init): blocks 0..15 -> W2 GEMM + Wk split + rowsum zero;
//      blocks 16..  -> x split to bf16 hi/lo (+ first 512 also zero g_St) ----
__global__ void __launch_bounds__(256)
k_init(const float* __restrict__ x,
       const float* __restrict__ w_proj, const float* __restrict__ w_qkv)
{
    if (blockIdx.x >= 16) {
        const size_t i = (size_t)(blockIdx.x - 16) * 256 + threadIdx.x;
        if (i < (size_t)BB * CC * CC / 4)
            *(float4*)(g_St + 4 * i) = make_float4(0.f, 0.f, 0.f, 0.f);
        float4 f = ((const float4*)x)[i];
        uint32_t l0, l1;
        uint32_t h0 = pack2(f.x, f.y, l0);
        uint32_t h1 = pack2(f.z, f.w, l1);
        *(uint2*)(g_xh + 4 * i) = make_uint2(h0, h1);
        *(uint2*)(g_xl + 4 * i) = make_uint2(l0, l1);
        return;
    }
    // --- W2 block path ---
    const int gt = blockIdx.x * 256 + threadIdx.x;   // 0..4095
    #pragma unroll
    for (int i = 0; i < 16; i++) {
        const int idx = gt + i * 4096;
        float v = w_qkv[CC * CC + idx];
        __nv_bfloat16 h = __float2bfloat16(v);
        g_Wkh[idx] = h;
        g_Wkl[idx] = __float2bfloat16(v - __bfloat162float(h));
    }
    if (gt < BB * CC) g_rowsum[gt] = 0.f;

    const int m0 = (blockIdx.x >> 2) * 64, n0 = (blockIdx.x & 3) * 64;
    float acc[4][4] = {};
    core64<false>(w_proj + (size_t)m0 * CC, CC,
                  w_qkv + (size_t)2 * CC * CC + n0, CC, nullptr, acc);
    const int tx = threadIdx.x & 15, ty = threadIdx.x >> 4;
    #pragma unroll
    for (int i = 0; i < 4; i++)
        #pragma unroll
        for (int j = 0; j < 4; j++)
            g_W2[(m0 + ty * 4 + i) * CC + n0 + tx * 4 + j] = acc[i][j];
}

__global__ void __launch_bounds__(256)
k_r(const float* __restrict__ w_qkv)
{
    const int b = blockIdx.z, m0 = blockIdx.y * 64, n0 = blockIdx.x * 64;
    float acc[4][4] = {};
    core64<true>(g_St + (size_t)b * CC * CC + (size_t)m0 * CC, CC,
                 w_qkv + n0, CC, g_rowsum + b * CC, acc);
    const int tx = threadIdx.x & 15, ty = threadIdx.x >> 4;
    float* Rb = g_R + (size_t)b * CC * CC;
    #pragma unroll
    for (int i = 0; i < 4; i++)
        #pragma unroll
        for (int j = 0; j < 4; j++)
            Rb[(m0 + ty * 4 + i) * CC + n0 + tx * 4 + j] = acc[i][j];
}

__global__ void __launch_bounds__(256)
k_m(const float* __restrict__ gamma, const float* __restrict__ var)
{
    const int b = blockIdx.z, m0 = blockIdx.y * 64, n0 = blockIdx.x * 64;
    float acc[4][4] = {};
    core64<false>(g_W2 + (size_t)m0 * CC, CC,
                  g_R + (size_t)b * CC * CC + n0, CC, nullptr, acc);
    const int tx = threadIdx.x & 15, ty = threadIdx.x >> 4;
    __nv_bfloat16* Mh = g_Mh + (size_t)b * CC * CC;
    __nv_bfloat16* Ml = g_Ml + (size_t)b * CC * CC;
    #pragma unroll
    for (int i = 0; i < 4; i++) {
        const int o = m0 + ty * 4 + i;
        const float inv = gamma[o] * rsqrtf(var[o] + EPS);
        #pragma unroll
        for (int j = 0; j < 4; j++) {
            float v = inv * acc[i][j];
            __nv_bfloat16 h = __float2bfloat16(v);
            Mh[o * CC + n0 + tx * 4 + j] = h;
            Ml[o * CC + n0 + tx * 4 + j] = __float2bfloat16(v - __bfloat162float(h));
        }
    }
}

// ---------------- launch ----------------
extern "C" void kernel_launch(void* const* d_in, const int* in_sizes, int n_in,
                              void* d_out, int out_size)
{
    const float* x      = (const float*)d_in[0];
    const float* w_qkv  = (const float*)d_in[1];
    const float* w_proj = (const float*)d_in[2];
    const float* gamma  = (const float*)d_in[3];
    const float* beta   = (const float*)d_in[4];
    const float* mean   = (const float*)d_in[5];
    const float* var    = (const float*)d_in[6];
    float* out = (float*)d_out;

    cudaFuncSetAttribute(k_exp, cudaFuncAttributeMaxDynamicSharedMemorySize, NN_SMEM);
    cudaFuncSetAttribute(k_out, cudaFuncAttributeMaxDynamicSharedMemorySize, NN_SMEM);
    cudaFuncSetAttribute(k_st,  cudaFuncAttributeMaxDynamicSharedMemorySize, NT_SMEM);

    dim3 blk(256);
    // fused: x split + g_St zero (32768 blocks) + W2/Wk/rowsum (16 blocks)
    k_init<<<dim3(16 + (size_t)BB * CC * NSP / 1024), blk>>>(x, w_proj, w_qkv);
    k_exp<<<dim3(NSP / 128, 2, BB), blk, NN_SMEM>>>();
    k_st<<<dim3(2, 2, BB * KSPLIT), blk, NT_SMEM>>>();
    k_r<<<dim3(4, 4, BB), blk>>>(w_qkv);
    k_m<<<dim3(4, 4, BB), blk>>>(gamma, var);
    k_out<<<dim3(NSP / 128, 2, BB), blk, NN_SMEM>>>(gamma, beta, mean, var, out);
}